// round 15
// baseline (speedup 1.0000x reference)
#include <cuda_runtime.h>
#include <cuda_bf16.h>
#include <cstdint>

#define BB    8
#define NN    4096
#define KNB   20
#define NPTS  (BB * NN)          /* 32768  */
#define M1    (NPTS * KNB)       /* 655360 */
#define EPSB  1e-5f

/* ================= static device scratch (no allocations) ============= */
__device__ int   g_idx[M1];                         /* knn indices          */
__device__ float g_cat[(size_t)NPTS * 192];         /* [x1|x2] [P,192]      */
__device__ float g_w2t[64 * 128];                   /* W2^T [k][o]          */
__device__ float g_w3t[192 * 256];                  /* W3^T [k][o]          */
__device__ __nv_bfloat16 g_w2hi[128 * 64];          /* W2 bf16 hi [o][k]    */
__device__ __nv_bfloat16 g_w2lo[128 * 64];          /* W2 bf16 lo [o][k]    */
__device__ __nv_bfloat16 g_w3hi[256 * 192];         /* W3 bf16 hi [o][k]    */
__device__ __nv_bfloat16 g_w3lo[256 * 192];         /* W3 bf16 lo [o][k]    */
__device__ float g_fpart[128 * 27];                 /* feat gram partials   */
__device__ float g_colpart[64 * 640];               /* h1 colsum partials   */
__device__ float g_gpart[(size_t)640 * 4096];       /* h1 gram partials     */
__device__ float g_gram[4096];                      /* h1 gram 64x64        */
__device__ float g_h1colsum[64];
__device__ float g_cpart[(size_t)64 * 36864];       /* cat gram partials    */
__device__ float g_cspart[192 * 128];               /* cat colsum partials  */
__device__ float g_cgram[36864];                    /* cat gram 192x192     */
__device__ float g_catsum[192];
__device__ float g_mu[448];                         /* L1:0 L2:64 L3:192    */
__device__ float g_rs[448];
__device__ unsigned int g_cnt0;                     /* fgram counter        */
__device__ unsigned int g_cnt1;                     /* gram2fin counter     */
__device__ unsigned int g_cnt2;                     /* catfin counter       */

/* ================= mma.sync / ldmatrix helpers (plain PTX ISA) ======= */
__device__ __forceinline__ uint32_t smem_u32(const void* p) {
    uint32_t a;
    asm("{ .reg .u64 t; cvta.to.shared.u64 t, %1; cvt.u32.u64 %0, t; }"
        : "=r"(a) : "l"(p));
    return a;
}
__device__ __forceinline__ void ldsm_x4(uint32_t* r, uint32_t addr) {
    asm volatile("ldmatrix.sync.aligned.m8n8.x4.shared.b16 {%0,%1,%2,%3}, [%4];"
                 : "=r"(r[0]), "=r"(r[1]), "=r"(r[2]), "=r"(r[3]) : "r"(addr));
}
__device__ __forceinline__ void ldsm_x2(uint32_t* r, uint32_t addr) {
    asm volatile("ldmatrix.sync.aligned.m8n8.x2.shared.b16 {%0,%1}, [%2];"
                 : "=r"(r[0]), "=r"(r[1]) : "r"(addr));
}
__device__ __forceinline__ void ldsm_x4_t(uint32_t* r, uint32_t addr) {
    asm volatile("ldmatrix.sync.aligned.m8n8.x4.trans.shared.b16 {%0,%1,%2,%3}, [%4];"
                 : "=r"(r[0]), "=r"(r[1]), "=r"(r[2]), "=r"(r[3]) : "r"(addr));
}
__device__ __forceinline__ void ldsm_x2_t(uint32_t* r, uint32_t addr) {
    asm volatile("ldmatrix.sync.aligned.m8n8.x2.trans.shared.b16 {%0,%1}, [%2];"
                 : "=r"(r[0]), "=r"(r[1]) : "r"(addr));
}
__device__ __forceinline__ void mma_bf16(float* d, const uint32_t* a,
                                         const uint32_t* b) {
    asm volatile(
        "mma.sync.aligned.m16n8k16.row.col.f32.bf16.bf16.f32 "
        "{%0,%1,%2,%3}, {%4,%5,%6,%7}, {%8,%9}, {%0,%1,%2,%3};"
        : "+f"(d[0]), "+f"(d[1]), "+f"(d[2]), "+f"(d[3])
        : "r"(a[0]), "r"(a[1]), "r"(a[2]), "r"(a[3]), "r"(b[0]), "r"(b[1]));
}
__device__ __forceinline__ void split4(float4 v, uint2* hi, uint2* lo) {
    __nv_bfloat16 hx = __float2bfloat16(v.x), hy = __float2bfloat16(v.y);
    __nv_bfloat16 hz = __float2bfloat16(v.z), hw = __float2bfloat16(v.w);
    __nv_bfloat16 lx = __float2bfloat16(v.x - __bfloat162float(hx));
    __nv_bfloat16 ly = __float2bfloat16(v.y - __bfloat162float(hy));
    __nv_bfloat16 lz = __float2bfloat16(v.z - __bfloat162float(hz));
    __nv_bfloat16 lw = __float2bfloat16(v.w - __bfloat162float(hw));
    __nv_bfloat162 h01, h23, l01, l23;
    h01.x = hx; h01.y = hy; h23.x = hz; h23.y = hw;
    l01.x = lx; l01.y = ly; l23.x = lz; l23.y = lw;
    hi->x = *(uint32_t*)&h01; hi->y = *(uint32_t*)&h23;
    lo->x = *(uint32_t*)&l01; lo->y = *(uint32_t*)&l23;
}

/* ================= prep: transposes + bf16 splits ==================== */
__global__ void prep_kernel(const float* __restrict__ W2,
                            const float* __restrict__ W3) {
    int t = blockIdx.x * blockDim.x + threadIdx.x;
    if (t < 64 * 128) {
        int k = t / 128, o = t % 128;
        g_w2t[t] = W2[o * 64 + k];
        float w = W2[t];
        __nv_bfloat16 hi = __float2bfloat16(w);
        g_w2hi[t] = hi;
        g_w2lo[t] = __float2bfloat16(w - __bfloat162float(hi));
    }
    if (t < 192 * 256) {
        int k = t / 256, o = t % 256;
        g_w3t[t] = W3[o * 192 + k];
        float w = W3[t];
        __nv_bfloat16 hi = __float2bfloat16(w);
        g_w3hi[t] = hi;
        g_w3lo[t] = __float2bfloat16(w - __bfloat162float(hi));
    }
}

/* ================= kNN: branch-light buffered top-20 ================= */
#define KTILE 1024
#define BUFSZ 64

__device__ __forceinline__ void ins20(float v, int id, float* s, int* si) {
    bool c[20];
#pragma unroll
    for (int t = 0; t < 20; ++t) c[t] = v > s[t];
#pragma unroll
    for (int t = 19; t >= 1; --t) {
        float nv = c[t - 1] ? s[t - 1] : v;
        int   ni = c[t - 1] ? si[t - 1] : id;
        s[t]  = c[t] ? nv : s[t];
        si[t] = c[t] ? ni : si[t];
    }
    s[0]  = c[0] ? v : s[0];
    si[0] = c[0] ? id : si[0];
}

__global__ void knn_kernel(const float* __restrict__ x) {
    __shared__ float4 pts[KTILE];
    const int b = blockIdx.x;
    const int n = blockIdx.y * blockDim.x + threadIdx.x;
    const float* xb = x + b * 3 * NN;
    const float qx = xb[n], qy = xb[NN + n], qz = xb[2 * NN + n];
    const float q2x = 2.f * qx, q2y = 2.f * qy, q2z = 2.f * qz;

    float s[20];
    int   si[20];
#pragma unroll
    for (int t = 0; t < 20; ++t) { s[t] = -3.0e38f; si[t] = 0; }
    float thr = -3.0e38f;

    float bufv[BUFSZ];
    int   bufi[BUFSZ];
    int   cnt = 0;

    for (int base = 0; base < NN; base += KTILE) {
        __syncthreads();
        for (int m = threadIdx.x; m < KTILE; m += blockDim.x) {
            float px = xb[base + m], py = xb[NN + base + m], pz = xb[2 * NN + base + m];
            pts[m] = make_float4(px, py, pz, fmaf(px, px, fmaf(py, py, pz * pz)));
        }
        __syncthreads();

        for (int g = 0; g < KTILE; g += 32) {
#pragma unroll
            for (int j = 0; j < 32; ++j) {
                float4 p = pts[g + j];
                float v = fmaf(q2x, p.x, fmaf(q2y, p.y, fmaf(q2z, p.z, -p.w)));
                if (v > thr) { bufv[cnt] = v; bufi[cnt] = base + g + j; ++cnt; }
            }
            if (__any_sync(0xffffffffu, cnt >= 32)) {
                int mx = cnt;
#pragma unroll
                for (int o = 16; o; o >>= 1)
                    mx = max(mx, __shfl_xor_sync(0xffffffffu, mx, o));
                for (int q = 0; q < mx; ++q) {
                    float v = (q < cnt) ? bufv[q] : -3.2e38f;
                    int   i = (q < cnt) ? bufi[q] : 0;
                    ins20(v, i, s, si);
                }
                cnt = 0;
                thr = s[19];
            }
        }
    }
    {
        int mx = cnt;
#pragma unroll
        for (int o = 16; o; o >>= 1)
            mx = max(mx, __shfl_xor_sync(0xffffffffu, mx, o));
        for (int q = 0; q < mx; ++q) {
            float v = (q < cnt) ? bufv[q] : -3.2e38f;
            int   i = (q < cnt) ? bufi[q] : 0;
            ins20(v, i, s, si);
        }
    }
    int* op = g_idx + (size_t)(b * NN + n) * KNB;
#pragma unroll
    for (int t = 0; t < 20; ++t) op[t] = si[t];
}

/* ================= feat Gram per-point + fused BN1 finalize ========== */
__global__ void fgram_kernel(const float* __restrict__ x,
                             const float* __restrict__ W1) {
    __shared__ float sm[8][27];
    __shared__ float part[27][8];
    __shared__ float gf[27];
    __shared__ int   isLast;
    const int t = threadIdx.x;
    const int p = blockIdx.x * 256 + t;
    const int b = p >> 12, n = p & (NN - 1);
    const float* xb = x + b * 3 * NN;
    const float cx = xb[n], cy = xb[NN + n], cz = xb[2 * NN + n];
    const int* ip = g_idx + (size_t)p * KNB;

    float s[27];
#pragma unroll
    for (int v = 0; v < 27; ++v) s[v] = 0.f;

#pragma unroll 4
    for (int k = 0; k < KNB; ++k) {
        const int nb = ip[k];
        float f[6];
        f[0] = xb[nb] - cx;
        f[1] = xb[NN + nb] - cy;
        f[2] = xb[2 * NN + nb] - cz;
        f[3] = cx; f[4] = cy; f[5] = cz;
        int u = 0;
#pragma unroll
        for (int i = 0; i < 6; ++i) {
            s[21 + i] += f[i];
#pragma unroll
            for (int j = 0; j <= i; ++j) s[u++] = fmaf(f[i], f[j], s[u]);
        }
    }
#pragma unroll
    for (int off = 16; off; off >>= 1)
#pragma unroll
        for (int v = 0; v < 27; ++v)
            s[v] += __shfl_xor_sync(0xffffffffu, s[v], off);

    if ((t & 31) == 0)
#pragma unroll
        for (int v = 0; v < 27; ++v) sm[t >> 5][v] = s[v];
    __syncthreads();
    if (t < 27) {
        float a = 0.f;
#pragma unroll
        for (int w = 0; w < 8; ++w) a += sm[w][t];
        g_fpart[blockIdx.x * 27 + t] = a;
    }

    __threadfence();
    if (t == 0) isLast = (atomicAdd(&g_cnt0, 1u) == 127u);
    __syncthreads();
    if (!isLast) return;
    if (t == 0) g_cnt0 = 0;

    if (t < 216) {
        int j = t / 8, sl = t % 8;
        float a = 0.f;
        for (int i = sl; i < 128; i += 8) a += g_fpart[i * 27 + j];
        part[j][sl] = a;
    }
    __syncthreads();
    if (t < 27) {
        float a = 0.f;
#pragma unroll
        for (int sl = 0; sl < 8; ++sl) a += part[t][sl];
        gf[t] = a;
    }
    __syncthreads();
    if (t < 64) {
        float w[6];
#pragma unroll
        for (int c = 0; c < 6; ++c) w[c] = W1[t * 6 + c];
        const float invM = 1.f / (float)M1;
        float mu = 0.f;
#pragma unroll
        for (int i = 0; i < 6; ++i) mu = fmaf(w[i], gf[21 + i], mu);
        mu *= invM;
        float q = 0.f;
#pragma unroll
        for (int i = 0; i < 6; ++i)
#pragma unroll
            for (int j = 0; j <= i; ++j) {
                float val = gf[i * (i + 1) / 2 + j];
                float c = w[i] * w[j] * val;
                q += (i == j) ? c : 2.f * c;
            }
        q *= invM;
        g_mu[t] = mu;
        g_rs[t] = rsqrtf(q - mu * mu + EPSB);
    }
}

/* ================= h1 Gram via HMMA hi/lo, 128-edge chunks =========== */
#define HG_ROWB 272
__global__ __launch_bounds__(256) void h1gram_hmma(
        const float* __restrict__ x,  const float* __restrict__ W1,
        const float* __restrict__ g1, const float* __restrict__ b1) {
    __shared__ float f6[2][128][8];
    __shared__ __align__(16) char thi[64 * HG_ROWB];
    __shared__ __align__(16) char tlo[64 * HG_ROWB];
    __shared__ float redc[4][64];
    const int t = threadIdx.x;
    const int w = t >> 5, lane = t & 31;
    const uint32_t uthi = smem_u32(thi), utlo = smem_u32(tlo);
    const int mrow = (w & 3) * 16;
    const int ncol = (w >> 2) * 32;

    const int c  = t & 63;
    const int eg = t >> 6;
    float wr[6];
#pragma unroll
    for (int j = 0; j < 6; ++j) wr[j] = W1[c * 6 + j];
    const float mu = g_mu[c], rsv = g_rs[c], gg = g1[c], bb = b1[c];

    float acc[4][4];
#pragma unroll
    for (int i = 0; i < 4; ++i)
#pragma unroll
        for (int j = 0; j < 4; ++j) acc[i][j] = 0.f;
    float cs = 0.f;

    if (t < 128) {
        int m = blockIdx.x * 1024 + t;
        int p = m / KNB, b_ = p >> 12, n_ = p & (NN - 1);
        const float* xb = x + b_ * 3 * NN;
        int nb = g_idx[m];
        float cx = xb[n_], cy = xb[NN + n_], cz = xb[2 * NN + n_];
        f6[0][t][0] = xb[nb] - cx;
        f6[0][t][1] = xb[NN + nb] - cy;
        f6[0][t][2] = xb[2 * NN + nb] - cz;
        f6[0][t][3] = cx; f6[0][t][4] = cy; f6[0][t][5] = cz;
    }

    for (int cc = 0; cc < 8; ++cc) {
        const int cur = cc & 1;
        __syncthreads();
        if (cc + 1 < 8 && t < 128) {
            int m = blockIdx.x * 1024 + (cc + 1) * 128 + t;
            int p = m / KNB, b_ = p >> 12, n_ = p & (NN - 1);
            const float* xb = x + b_ * 3 * NN;
            int nb = g_idx[m];
            float cx = xb[n_], cy = xb[NN + n_], cz = xb[2 * NN + n_];
            f6[cur ^ 1][t][0] = xb[nb] - cx;
            f6[cur ^ 1][t][1] = xb[NN + nb] - cy;
            f6[cur ^ 1][t][2] = xb[2 * NN + nb] - cz;
            f6[cur ^ 1][t][3] = cx; f6[cur ^ 1][t][4] = cy; f6[cur ^ 1][t][5] = cz;
        }
#pragma unroll 4
        for (int i = 0; i < 32; ++i) {
            const int e = eg + i * 4;
            const float* f = f6[cur][e];
            float y = wr[0] * f[0];
            y = fmaf(wr[1], f[1], y);
            y = fmaf(wr[2], f[2], y);
            y = fmaf(wr[3], f[3], y);
            y = fmaf(wr[4], f[4], y);
            y = fmaf(wr[5], f[5], y);
            float h = fmaxf(fmaf((y - mu) * rsv, gg, bb), 0.f);
            cs += h;
            __nv_bfloat16 hi = __float2bfloat16(h);
            __nv_bfloat16 lo = __float2bfloat16(h - __bfloat162float(hi));
            *(__nv_bfloat16*)(thi + c * HG_ROWB + e * 2) = hi;
            *(__nv_bfloat16*)(tlo + c * HG_ROWB + e * 2) = lo;
        }
        __syncthreads();

#pragma unroll
        for (int ks = 0; ks < 8; ++ks) {
            const uint32_t aoff = (uint32_t)(mrow + (lane & 15)) * HG_ROWB
                                + ((lane >> 4) & 1) * 16 + ks * 32;
            uint32_t ah[4], al[4];
            ldsm_x4(ah, uthi + aoff);
            ldsm_x4(al, utlo + aoff);
#pragma unroll
            for (int nt = 0; nt < 4; ++nt) {
                const uint32_t boff =
                    (uint32_t)(ncol + nt * 8 + (lane & 7)) * HG_ROWB
                    + ((lane >> 3) & 1) * 16 + ks * 32;
                uint32_t bh[2], bl[2];
                ldsm_x2(bh, uthi + boff);
                ldsm_x2(bl, utlo + boff);
                mma_bf16(acc[nt], ah, bh);
                mma_bf16(acc[nt], ah, bl);
                mma_bf16(acc[nt], al, bh);
            }
        }
    }
    redc[eg][c] = cs;
    __syncthreads();
    if (eg == 0)
        g_colpart[(size_t)c * 640 + blockIdx.x] =
            redc[0][c] + redc[1][c] + redc[2][c] + redc[3][c];

    float* gp = g_gpart + (size_t)blockIdx.x * 4096;
    const int r0 = mrow + (lane >> 2);
#pragma unroll
    for (int nt = 0; nt < 4; ++nt) {
        const int c0 = ncol + nt * 8 + (lane & 3) * 2;
        gp[r0 * 64 + c0]           = acc[nt][0];
        gp[r0 * 64 + c0 + 1]       = acc[nt][1];
        gp[(r0 + 8) * 64 + c0]     = acc[nt][2];
        gp[(r0 + 8) * 64 + c0 + 1] = acc[nt][3];
    }
}

/* ================= reduce h1 gram + colsum + fused BN2 =============== */
__global__ void gram2fin_kernel() {
    __shared__ float red[64][4];
    __shared__ float swv[8192];
    __shared__ int   isLast;
    const int t = threadIdx.x;
    const int e = t >> 2, sl = t & 3;
    if (blockIdx.x == 64) {
        float a = 0.f;
        for (int i = sl; i < 640; i += 4) a += g_colpart[(size_t)e * 640 + i];
        red[e][sl] = a;
        __syncthreads();
        if (sl == 0)
            g_h1colsum[e] = red[e][0] + red[e][1] + red[e][2] + red[e][3];
    } else {
        const int ge = blockIdx.x * 64 + e;
        float a = 0.f;
        for (int i = sl; i < 640; i += 4) a += g_gpart[(size_t)i * 4096 + ge];
        red[e][sl] = a;
        __syncthreads();
        if (sl == 0)
            g_gram[ge] = red[e][0] + red[e][1] + red[e][2] + red[e][3];
    }

    /* ---- last-block BN2 finalize ---- */
    __threadfence();
    if (t == 0) isLast = (atomicAdd(&g_cnt1, 1u) == 64u);
    __syncthreads();
    if (!isLast) return;
    if (t == 0) g_cnt1 = 0;

    for (int idx = t; idx < 8192; idx += 256) swv[idx] = g_w2t[idx];
    __syncthreads();
    if (t < 128) {
        const int o = t;
        const float invM = 1.f / (float)M1;
        float mu = 0.f, q = 0.f;
        for (int i = 0; i < 64; ++i) {
            float wi = swv[i * 128 + o];
            mu = fmaf(wi, g_h1colsum[i], mu);
            float qi = 0.f;
            const float* Gi = g_gram + i * 64;
#pragma unroll 8
            for (int j = 0; j < 64; ++j)
                qi = fmaf(Gi[j], swv[j * 128 + o], qi);
            q = fmaf(wi, qi, q);
        }
        mu *= invM;
        float var = q * invM - mu * mu;
        g_mu[64 + o] = mu;
        g_rs[64 + o] = rsqrtf(var + EPSB);
    }
}

/* ================= GEMM2 via mma.sync bf16 hi/lo + x1 & x2 pool ====== */
#define G2_ROWB   144
#define G2_OFF_F6   0
#define G2_OFF_WHI  5120
#define G2_OFF_WLO  (G2_OFF_WHI + 128 * G2_ROWB)
#define G2_OFF_BHI  (G2_OFF_WLO + 128 * G2_ROWB)
#define G2_OFF_BLO  (G2_OFF_BHI + 160 * G2_ROWB)
#define G2_OFF_SLAB (G2_OFF_BLO + 160 * G2_ROWB)
#define G2_SLABW    (16 * 44 * 4)
#define G2_SMEM     (G2_OFF_SLAB + 8 * G2_SLABW)

__global__ __launch_bounds__(256) void gemm2pool_hmma(
        const float* __restrict__ x,  const float* __restrict__ W1,
        const float* __restrict__ g1, const float* __restrict__ b1,
        const float* __restrict__ g2, const float* __restrict__ b2v) {
    extern __shared__ __align__(16) char smem[];
    const int t = threadIdx.x;
    const int w = t >> 5, lane = t & 31;
    const uint32_t sbase = smem_u32(smem);
    float* f6 = (float*)(smem + G2_OFF_F6);

    if (t < 160) {
        int m = blockIdx.x * 160 + t;
        int p = m / KNB, b_ = p >> 12, n_ = p & (NN - 1);
        const float* xb = x + b_ * 3 * NN;
        int nb = g_idx[m];
        float cx = xb[n_], cy = xb[NN + n_], cz = xb[2 * NN + n_];
        f6[t * 8 + 0] = xb[nb] - cx;
        f6[t * 8 + 1] = xb[NN + nb] - cy;
        f6[t * 8 + 2] = xb[2 * NN + nb] - cz;
        f6[t * 8 + 3] = cx; f6[t * 8 + 4] = cy; f6[t * 8 + 5] = cz;
    }
#pragma unroll
    for (int l = 0; l < 4; ++l) {
        int q = t + 256 * l;
        int r = q >> 3, c16 = q & 7;
        *(uint4*)(smem + G2_OFF_WHI + r * G2_ROWB + c16 * 16) = ((const uint4*)g_w2hi)[q];
        *(uint4*)(smem + G2_OFF_WLO + r * G2_ROWB + c16 * 16) = ((const uint4*)g_w2lo)[q];
    }
    __syncthreads();

    {
        const int c  = t & 63;
        const int eg = t >> 6;
        float wr[6];
#pragma unroll
        for (int j = 0; j < 6; ++j) wr[j] = W1[c * 6 + j];
        const float mu = g_mu[c], rsv = g_rs[c], gg = g1[c], bb = b1[c];
#pragma unroll 4
        for (int i = 0; i < 40; ++i) {
            const int e = eg + i * 4;
            const float* f = f6 + e * 8;
            float y = wr[0] * f[0];
            y = fmaf(wr[1], f[1], y);
            y = fmaf(wr[2], f[2], y);
            y = fmaf(wr[3], f[3], y);
            y = fmaf(wr[4], f[4], y);
            y = fmaf(wr[5], f[5], y);
            float h = fmaxf(fmaf((y - mu) * rsv, gg, bb), 0.f);
            __nv_bfloat16 hi = __float2bfloat16(h);
            __nv_bfloat16 lo = __float2bfloat16(h - __bfloat162float(hi));
            *(__nv_bfloat16*)(smem + G2_OFF_BHI + e * G2_ROWB + c * 2) = hi;
            *(__nv_bfloat16*)(smem + G2_OFF_BLO + e * G2_ROWB + c * 2) = lo;
        }
    }
    __syncthreads();

    /* x1 pooling from reconstructed h1 (hi+lo) */
#pragma unroll
    for (int task = t; task < 512; task += 256) {
        const int pl = task >> 6;
        const int c  = task & 63;
        const char* ph = smem + G2_OFF_BHI + c * 2;
        const char* pl2 = smem + G2_OFF_BLO + c * 2;
        float h[20], hmax = 0.f;
#pragma unroll
        for (int k = 0; k < 20; ++k) {
            const int e = pl * 20 + k;
            float hv = __bfloat162float(*(const __nv_bfloat16*)(ph + (size_t)e * G2_ROWB))
                     + __bfloat162float(*(const __nv_bfloat16*)(pl2 + (size_t)e * G2_ROWB));
            h[k] = hv;
            hmax = fmaxf(hmax, hv);
        }
        float se = 0.f, sw = 0.f;
#pragma unroll
        for (int k = 0; k < 20; ++k) {
            float e = __expf(h[k] - hmax);
            se += e;
            sw = fmaf(e, h[k], sw);
        }
        g_cat[(size_t)(blockIdx.x * 8 + pl) * 192 + c] = sw / se;
    }

    const int cbase = w * 16;
    uint32_t ahi[4][4], alo[4][4];
    {
        const uint32_t arow = (uint32_t)(cbase + (lane & 15)) * G2_ROWB
                            + ((lane >> 4) & 1) * 16;
#pragma unroll
        for (int kc = 0; kc < 4; ++kc) {
            ldsm_x4(ahi[kc], sbase + G2_OFF_WHI + arow + kc * 32);
            ldsm_x4(alo[kc], sbase + G2_OFF_WLO + arow + kc * 32);
        }
    }

    const int pch = cbase + (lane & 15);
    const float mu2 = g_mu[64 + pch], rs2 = g_rs[64 + pch];
    const float gg2 = g2[pch], bb2 = b2v[pch];
    float* slab = (float*)(smem + G2_OFF_SLAB + w * G2_SLABW);

#pragma unroll
    for (int grp = 0; grp < 4; ++grp) {
        float D[5][4];
#pragma unroll
        for (int nt = 0; nt < 5; ++nt)
#pragma unroll
            for (int j = 0; j < 4; ++j) D[nt][j] = 0.f;

#pragma unroll
        for (int nt = 0; nt < 5; ++nt) {
            const int ebase = grp * 40 + nt * 8;
            const uint32_t brow = (uint32_t)(ebase + (lane & 7)) * G2_ROWB
                                + ((lane >> 3) & 1) * 16;
#pragma unroll
            for (int kc = 0; kc < 4; ++kc) {
                uint32_t bh[2], bl[2];
                ldsm_x2(bh, sbase + G2_OFF_BHI + brow + kc * 32);
                ldsm_x2(bl, sbase + G2_OFF_BLO + brow + kc * 32);
                mma_bf16(D[nt], ahi[kc], bh);
                mma_bf16(D[nt], ahi[kc], bl);
                mma_bf16(D[nt], alo[kc], bh);
            }
        }
        {
            const int r0 = lane >> 2;
            const int c0 = 2 * (lane & 3);
#pragma unroll
            for (int nt = 0; nt < 5; ++nt) {
                const int col = nt * 8 + c0;
                slab[r0 * 44 + col]           = D[nt][0];
                slab[r0 * 44 + col + 1]       = D[nt][1];
                slab[(r0 + 8) * 44 + col]     = D[nt][2];
                slab[(r0 + 8) * 44 + col + 1] = D[nt][3];
            }
        }
        __syncwarp();
        {
            const int ch = lane & 15;
            const int ph = lane >> 4;
            const float* row = slab + ch * 44 + ph * 20;
            float h[20], hmax = 0.f;
#pragma unroll
            for (int k = 0; k < 20; ++k) {
                float y = row[k];
                h[k] = fmaxf(fmaf((y - mu2) * rs2, gg2, bb2), 0.f);
                hmax = fmaxf(hmax, h[k]);
            }
            float se = 0.f, sw = 0.f;
#pragma unroll
            for (int k = 0; k < 20; ++k) {
                float e = __expf(h[k] - hmax);
                se += e;
                sw = fmaf(e, h[k], sw);
            }
            const int p = blockIdx.x * 8 + grp * 2 + ph;
            g_cat[(size_t)p * 192 + 64 + pch] = sw / se;
        }
        __syncwarp();
    }
}

/* ================= cat Gram (192x192) via HMMA + ldmatrix.trans ====== */
#define CG_ROWB 400
__global__ __launch_bounds__(256) void catgram_trans() {
    __shared__ __align__(16) char thi[32 * CG_ROWB];
    __shared__ __align__(16) char tlo[32 * CG_ROWB];
    const int t = threadIdx.x;
    const int w = t >> 5, lane = t & 31;
    const uint32_t uthi = smem_u32(thi), utlo = smem_u32(tlo);
    const int mrow = (w & 3) * 48;
    const int nch  = blockIdx.y * 64 + (w >> 2) * 32;

    float acc[3][4][4];
#pragma unroll
    for (int mt = 0; mt < 3; ++mt)
#pragma unroll
        for (int nt = 0; nt < 4; ++nt)
#pragma unroll
            for (int j = 0; j < 4; ++j) acc[mt][nt][j] = 0.f;

    for (int cc = 0; cc < 16; ++cc) {
        const int rowbase = blockIdx.x * 512 + cc * 32;
        __syncthreads();
#pragma unroll
        for (int l = 0; l < 6; ++l) {
            int q = t + 256 * l;
            int r = q / 48, cg = q % 48;
            float4 v = *(const float4*)(g_cat + (size_t)(rowbase + r) * 192 + cg * 4);
            uint2 hi, lo;
            split4(v, &hi, &lo);
            *(uint2*)(thi + r * CG_ROWB + cg * 8) = hi;
            *(uint2*)(tlo + r * CG_ROWB + cg * 8) = lo;
        }
        __syncthreads();

#pragma unroll
        for (int ks = 0; ks < 2; ++ks) {
            const int rb = ks * 16;
            uint32_t ah[3][4], al[3][4];
#pragma unroll
            for (int mt = 0; mt < 3; ++mt) {
                const int cb = mrow + mt * 16;
                const uint32_t aoff =
                    (uint32_t)(rb + ((lane >> 4) & 1) * 8 + (lane & 7)) * CG_ROWB
                    + (uint32_t)(cb + ((lane >> 3) & 1) * 8) * 2;
                ldsm_x4_t(ah[mt], uthi + aoff);
                ldsm_x4_t(al[mt], utlo + aoff);
            }
#pragma unroll
            for (int nt = 0; nt < 4; ++nt) {
                const int nb = nch + nt * 8;
                const uint32_t boff =
                    (uint32_t)(rb + ((lane >> 3) & 1) * 8 + (lane & 7)) * CG_ROWB
                    + (uint32_t)nb * 2;
                uint32_t bh[2], bl[2];
                ldsm_x2_t(bh, uthi + boff);
                ldsm_x2_t(bl, utlo + boff);
#pragma unroll
                for (int mt = 0; mt < 3; ++mt) {
                    mma_bf16(acc[mt][nt], ah[mt], bh);
                    mma_bf16(acc[mt][nt], ah[mt], bl);
                    mma_bf16(acc[mt][nt], al[mt], bh);
                }
            }
        }
    }
    float* gp = g_cpart + (size_t)blockIdx.x * 36864;
#pragma unroll
    for (int mt = 0; mt < 3; ++mt) {
        const int r0 = mrow + mt * 16 + (lane >> 2);
#pragma unroll
        for (int nt = 0; nt < 4; ++nt) {
            const int c0 = nch + nt * 8 + (lane & 3) * 2;
            gp[r0 * 192 + c0]             = acc[mt][nt][0];
            gp[r0 * 192 + c0 + 1]         = acc[mt][nt][1];
            gp[(r0 + 8) * 192 + c0]       = acc[mt][nt][2];
            gp[(r0 + 8) * 192 + c0 + 1]   = acc[mt][nt][3];
        }
    }
}

/* ================= catfin: colsum + cgram reduce + catsum finalize === */
__global__ void catfin_kernel() {
    __shared__ int isLast;
    const int t = threadIdx.x;
    const int bx = blockIdx.x;

    /* colsum partial for rows [bx*256, bx*256+256) */
    if (t < 192) {
        const int r0 = bx * 256;
        float a = 0.f;
#pragma unroll 8
        for (int r = 0; r < 256; ++r)
            a += g_cat[(size_t)(r0 + r) * 192 + t];
        g_cspart[t * 128 + bx] = a;
    }

    /* cgram reduce: 288 elements per block */
    for (int k = t; k < 288; k += 256) {
        const int e = bx * 288 + k;
        float a = 0.f;
#pragma unroll 8
        for (int p = 0; p < 64; ++p) a += g_cpart[(size_t)p * 36864 + e];
        g_cgram[e] = a;
    }

    /* last-block catsum finalize */
    __threadfence();
    if (t == 0) isLast = (atomicAdd(&g_cnt2, 1u) == 127u);
    __syncthreads();
    if (!isLast) return;
    if (t == 0) g_cnt2 = 0;
    if (t < 192) {
        float a = 0.f;
#pragma unroll 8
        for (int p = 0; p < 128; ++p) a += g_cspart[t * 128 + p];
        g_catsum[t] = a;
    }
}

/* ================= BN3 stats from cat Gram =========================== */
__global__ void bn3fin_kernel() {
    const int o = blockIdx.x;
    const int i = threadIdx.x;
    __shared__ float w[192], rq[192], rm[192];
    w[i] = g_w3t[i * 256 + o];
    __syncthreads();
    float qi = 0.f;
    const float* Gi = g_cgram + i * 192;
#pragma unroll 8
    for (int j = 0; j < 192; ++j) qi = fmaf(Gi[j], w[j], qi);
    rq[i] = qi * w[i];
    rm[i] = w[i] * g_catsum[i];
    __syncthreads();
    for (int s = 96; s >= 3; s >>= 1) {
        if (i < s) { rq[i] += rq[i + s]; rm[i] += rm[i + s]; }
        __syncthreads();
    }
    if (i == 0) {
        const float invN = 1.f / (float)NPTS;
        float mu = (rm[0] + rm[1] + rm[2]) * invN;
        float var = (rq[0] + rq[1] + rq[2]) * invN - mu * mu;
        g_mu[192 + o] = mu;
        g_rs[192 + o] = rsqrtf(var + EPSB);
    }
}

/* ================= GEMM3 via HMMA hi/lo + BN3 + transposed out ======= */
#define G3_ROWB 144
#define G3_OFF_AHI 0
#define G3_OFF_ALO (G3_OFF_AHI + 128 * G3_ROWB)
#define G3_OFF_BHI (G3_OFF_ALO + 128 * G3_ROWB)
#define G3_OFF_BLO (G3_OFF_BHI + 128 * G3_ROWB)
#define G3_SMEM    (G3_OFF_BLO + 128 * G3_ROWB)

__global__ __launch_bounds__(256) void gemm3out_hmma(
        const float* __restrict__ g3, const float* __restrict__ b3,
        float* __restrict__ out) {
    extern __shared__ __align__(16) char smem[];
    const int t = threadIdx.x;
    const int w = t >> 5, lane = t & 31;
    const uint32_t sbase = smem_u32(smem);
    const int mbase = blockIdx.x * 128;
    const int nbase = blockIdx.y * 128;
    const int mrow = (w & 3) * 32;
    const int ncol = (w >> 2) * 64;

    float acc[2][8][4];
#pragma unroll
    for (int mt = 0; mt < 2; ++mt)
#pragma unroll
        for (int nt = 0; nt < 8; ++nt)
#pragma unroll
            for (int j = 0; j < 4; ++j) acc[mt][nt][j] = 0.f;

#pragma unroll
    for (int kc = 0; kc < 3; ++kc) {
#pragma unroll
        for (int l = 0; l < 8; ++l) {
            int q = t + 256 * l;
            int r = q >> 4, kq = (q & 15) * 4;
            float4 v = *(const float4*)(g_cat + (size_t)(mbase + r) * 192
                                        + kc * 64 + kq);
            uint2 hi, lo;
            split4(v, &hi, &lo);
            *(uint2*)(smem + G3_OFF_AHI + r * G3_ROWB + kq * 2) = hi;
            *(uint2*)(smem + G3_OFF_ALO + r * G3_ROWB + kq * 2) = lo;
        }
#pragma unroll
        for (int l = 0; l < 4; ++l) {
            int q = t + 256 * l;
            int r = q >> 3, c16 = q & 7;
            const char* srch = (const char*)g_w3hi
                + (size_t)(nbase + r) * 384 + kc * 128 + c16 * 16;
            const char* srcl = (const char*)g_w3lo
                + (size_t)(nbase + r) * 384 + kc * 128 + c16 * 16;
            *(uint4*)(smem + G3_OFF_BHI + r * G3_ROWB + c16 * 16) = *(const uint4*)srch;
            *(uint4*)(smem + G3_OFF_BLO + r * G3_ROWB + c16 * 16) = *(const uint4*)srcl;
        }
        __syncthreads();

#pragma unroll
        for (int ks = 0; ks < 4; ++ks) {
            uint32_t ah[2][4], al[2][4];
#pragma unroll
            for (int mt = 0; mt < 2; ++mt) {
                const uint32_t aoff =
                    (uint32_t)(mrow + mt * 16 + (lane & 15)) * G3_ROWB
                    + ((lane >> 4) & 1) * 16 + ks * 32;
                ldsm_x4(ah[mt], sbase + G3_OFF_AHI + aoff);
                ldsm_x4(al[mt], sbase + G3_OFF_ALO + aoff);
            }
#pragma unroll
            for (int nt = 0; nt < 8; ++nt) {
                const uint32_t boff =
                    (uint32_t)(ncol + nt * 8 + (lane & 7)) * G3_ROWB
                    + ((lane >> 3) & 1) * 16 + ks * 32;
                uint32_t bh[2], bl[2];
                ldsm_x2(bh, sbase + G3_OFF_BHI + boff);
                ldsm_x2(bl, sbase + G3_OFF_BLO + boff);
#pragma unroll
                for (int mt = 0; mt < 2; ++mt) {
                    mma_bf16(acc[mt][nt], ah[mt], bh);
                    mma_bf16(acc[mt][nt], ah[mt], bl);
                    mma_bf16(acc[mt][nt], al[mt], bh);
                }
            }
        }
        __syncthreads();
    }

    float* slab = (float*)smem;
#pragma unroll
    for (int mt = 0; mt < 2; ++mt) {
        const int r = mrow + mt * 16 + (lane >> 2);
#pragma unroll
        for (int nt = 0; nt < 8; ++nt) {
            const int cl = ncol + nt * 8 + (lane & 3) * 2;
            slab[cl * 132 + r]           = acc[mt][nt][0];
            slab[(cl + 1) * 132 + r]     = acc[mt][nt][1];
            slab[cl * 132 + r + 8]       = acc[mt][nt][2];
            slab[(cl + 1) * 132 + r + 8] = acc[mt][nt][3];
        }
    }
    __syncthreads();

    const int b = mbase >> 12;
    const int nloc = mbase & (NN - 1);
    const int cl = t >> 1;
    const int half = t & 1;
    const int o = nbase + cl;
    const float mu = g_mu[192 + o], rsv = g_rs[192 + o];
    const float gg = g3[o], bb = b3[o];
    const float* srow = slab + cl * 132 + half * 64;
    float* op = out + ((size_t)b * 256 + o) * NN + nloc + half * 64;
#pragma unroll
    for (int j = 0; j < 16; ++j) {
        float4 v = *(const float4*)(srow + j * 4);
        float4 r;
        r.x = fmaxf(fmaf((v.x - mu) * rsv, gg, bb), 0.f);
        r.y = fmaxf(fmaf((v.y - mu) * rsv, gg, bb), 0.f);
        r.z = fmaxf(fmaf((v.z - mu) * rsv, gg, bb), 0.f);
        r.w = fmaxf(fmaf((v.w - mu) * rsv, gg, bb), 0.f);
        *(float4*)(op + j * 4) = r;
    }
}

/* ================= launcher ========================================== */
extern "C" void kernel_launch(void* const* d_in, const int* in_sizes, int n_in,
                              void* d_out, int out_size) {
    const float* x  = (const float*)d_in[0];
    const float* W1 = (const float*)d_in[1];
    const float* g1 = (const float*)d_in[2];
    const float* b1 = (const float*)d_in[3];
    const float* W2 = (const float*)d_in[4];
    const float* g2 = (const float*)d_in[5];
    const float* b2 = (const float*)d_in[6];
    const float* W3 = (const float*)d_in[7];
    const float* g3 = (const float*)d_in[8];
    const float* b3 = (const float*)d_in[9];
    float* out = (float*)d_out;

    cudaFuncSetAttribute(gemm2pool_hmma,
                         cudaFuncAttributeMaxDynamicSharedMemorySize, G2_SMEM);
    cudaFuncSetAttribute(gemm3out_hmma,
                         cudaFuncAttributeMaxDynamicSharedMemorySize, G3_SMEM);

    prep_kernel<<<192, 256>>>(W2, W3);
    knn_kernel<<<dim3(BB, NN / 256), 256>>>(x);

    fgram_kernel<<<128, 256>>>(x, W1);           /* + BN1 finalize */

    h1gram_hmma<<<640, 256>>>(x, W1, g1, b1);    /* profiled slot  */
    gram2fin_kernel<<<65, 256>>>();              /* + BN2 finalize */

    gemm2pool_hmma<<<M1 / 160, 256, G2_SMEM>>>(x, W1, g1, b1, g2, b2);

    catgram_trans<<<dim3(64, 3), 256>>>();
    catfin_kernel<<<128, 256>>>();               /* colsum+reduce+finalize */
    bn3fin_kernel<<<256, 192>>>();

    gemm3out_hmma<<<dim3(NPTS / 128, 2), 256, G3_SMEM>>>(g3, b3, out);

    (void)in_sizes; (void)n_in; (void)out_size;
}

// round 16
// speedup vs baseline: 1.1587x; 1.1587x over previous
#include <cuda_runtime.h>
#include <cuda_bf16.h>
#include <cstdint>

#define BB    8
#define NN    4096
#define KNB   20
#define NPTS  (BB * NN)          /* 32768  */
#define M1    (NPTS * KNB)       /* 655360 */
#define EPSB  1e-5f

/* ================= static device scratch (no allocations) ============= */
__device__ int   g_idx[M1];                         /* knn indices          */
__device__ float g_cat[(size_t)NPTS * 192];         /* [x1|x2] [P,192]      */
__device__ float g_w2t[64 * 128];                   /* W2^T [k][o]          */
__device__ float g_w3t[192 * 256];                  /* W3^T [k][o]          */
__device__ __nv_bfloat16 g_w2hi[128 * 64];          /* W2 bf16 hi [o][k]    */
__device__ __nv_bfloat16 g_w2lo[128 * 64];          /* W2 bf16 lo [o][k]    */
__device__ __nv_bfloat16 g_w3hi[256 * 192];         /* W3 bf16 hi [o][k]    */
__device__ __nv_bfloat16 g_w3lo[256 * 192];         /* W3 bf16 lo [o][k]    */
__device__ float g_fpart[128 * 27];                 /* feat gram partials   */
__device__ float g_colpart[64 * 640];               /* h1 colsum partials   */
__device__ float g_gpart[(size_t)640 * 4096];       /* h1 gram partials     */
__device__ float g_gram[4096];                      /* h1 gram 64x64        */
__device__ float g_h1colsum[64];
__device__ float g_cpart[(size_t)64 * 36864];       /* cat gram partials    */
__device__ float g_cspart[192 * 128];               /* cat colsum partials  */
__device__ float g_cgram[36864];                    /* cat gram 192x192     */
__device__ float g_catsum[192];
__device__ float g_mu[448];                         /* L1:0 L2:64 L3:192    */
__device__ float g_rs[448];
__device__ unsigned int g_cnt0;                     /* fgram counter        */

/* ================= mma.sync / ldmatrix helpers (plain PTX ISA) ======= */
__device__ __forceinline__ uint32_t smem_u32(const void* p) {
    uint32_t a;
    asm("{ .reg .u64 t; cvta.to.shared.u64 t, %1; cvt.u32.u64 %0, t; }"
        : "=r"(a) : "l"(p));
    return a;
}
__device__ __forceinline__ void ldsm_x4(uint32_t* r, uint32_t addr) {
    asm volatile("ldmatrix.sync.aligned.m8n8.x4.shared.b16 {%0,%1,%2,%3}, [%4];"
                 : "=r"(r[0]), "=r"(r[1]), "=r"(r[2]), "=r"(r[3]) : "r"(addr));
}
__device__ __forceinline__ void ldsm_x2(uint32_t* r, uint32_t addr) {
    asm volatile("ldmatrix.sync.aligned.m8n8.x2.shared.b16 {%0,%1}, [%2];"
                 : "=r"(r[0]), "=r"(r[1]) : "r"(addr));
}
__device__ __forceinline__ void ldsm_x4_t(uint32_t* r, uint32_t addr) {
    asm volatile("ldmatrix.sync.aligned.m8n8.x4.trans.shared.b16 {%0,%1,%2,%3}, [%4];"
                 : "=r"(r[0]), "=r"(r[1]), "=r"(r[2]), "=r"(r[3]) : "r"(addr));
}
__device__ __forceinline__ void ldsm_x2_t(uint32_t* r, uint32_t addr) {
    asm volatile("ldmatrix.sync.aligned.m8n8.x2.trans.shared.b16 {%0,%1}, [%2];"
                 : "=r"(r[0]), "=r"(r[1]) : "r"(addr));
}
__device__ __forceinline__ void mma_bf16(float* d, const uint32_t* a,
                                         const uint32_t* b) {
    asm volatile(
        "mma.sync.aligned.m16n8k16.row.col.f32.bf16.bf16.f32 "
        "{%0,%1,%2,%3}, {%4,%5,%6,%7}, {%8,%9}, {%0,%1,%2,%3};"
        : "+f"(d[0]), "+f"(d[1]), "+f"(d[2]), "+f"(d[3])
        : "r"(a[0]), "r"(a[1]), "r"(a[2]), "r"(a[3]), "r"(b[0]), "r"(b[1]));
}
__device__ __forceinline__ void split4(float4 v, uint2* hi, uint2* lo) {
    __nv_bfloat16 hx = __float2bfloat16(v.x), hy = __float2bfloat16(v.y);
    __nv_bfloat16 hz = __float2bfloat16(v.z), hw = __float2bfloat16(v.w);
    __nv_bfloat16 lx = __float2bfloat16(v.x - __bfloat162float(hx));
    __nv_bfloat16 ly = __float2bfloat16(v.y - __bfloat162float(hy));
    __nv_bfloat16 lz = __float2bfloat16(v.z - __bfloat162float(hz));
    __nv_bfloat16 lw = __float2bfloat16(v.w - __bfloat162float(hw));
    __nv_bfloat162 h01, h23, l01, l23;
    h01.x = hx; h01.y = hy; h23.x = hz; h23.y = hw;
    l01.x = lx; l01.y = ly; l23.x = lz; l23.y = lw;
    hi->x = *(uint32_t*)&h01; hi->y = *(uint32_t*)&h23;
    lo->x = *(uint32_t*)&l01; lo->y = *(uint32_t*)&l23;
}

/* ================= prep: transposes + bf16 splits ==================== */
__global__ void prep_kernel(const float* __restrict__ W2,
                            const float* __restrict__ W3) {
    int t = blockIdx.x * blockDim.x + threadIdx.x;
    if (t < 64 * 128) {
        int k = t / 128, o = t % 128;
        g_w2t[t] = W2[o * 64 + k];
        float w = W2[t];
        __nv_bfloat16 hi = __float2bfloat16(w);
        g_w2hi[t] = hi;
        g_w2lo[t] = __float2bfloat16(w - __bfloat162float(hi));
    }
    if (t < 192 * 256) {
        int k = t / 256, o = t % 256;
        g_w3t[t] = W3[o * 192 + k];
        float w = W3[t];
        __nv_bfloat16 hi = __float2bfloat16(w);
        g_w3hi[t] = hi;
        g_w3lo[t] = __float2bfloat16(w - __bfloat162float(hi));
    }
}

/* ================= kNN: branch-light buffered top-20 ================= */
#define KTILE 1024
#define BUFSZ 64

__device__ __forceinline__ void ins20(float v, int id, float* s, int* si) {
    bool c[20];
#pragma unroll
    for (int t = 0; t < 20; ++t) c[t] = v > s[t];
#pragma unroll
    for (int t = 19; t >= 1; --t) {
        float nv = c[t - 1] ? s[t - 1] : v;
        int   ni = c[t - 1] ? si[t - 1] : id;
        s[t]  = c[t] ? nv : s[t];
        si[t] = c[t] ? ni : si[t];
    }
    s[0]  = c[0] ? v : s[0];
    si[0] = c[0] ? id : si[0];
}

__global__ void knn_kernel(const float* __restrict__ x) {
    __shared__ float4 pts[KTILE];
    const int b = blockIdx.x;
    const int n = blockIdx.y * blockDim.x + threadIdx.x;
    const float* xb = x + b * 3 * NN;
    const float qx = xb[n], qy = xb[NN + n], qz = xb[2 * NN + n];
    const float q2x = 2.f * qx, q2y = 2.f * qy, q2z = 2.f * qz;

    float s[20];
    int   si[20];
#pragma unroll
    for (int t = 0; t < 20; ++t) { s[t] = -3.0e38f; si[t] = 0; }
    float thr = -3.0e38f;

    float bufv[BUFSZ];
    int   bufi[BUFSZ];
    int   cnt = 0;

    for (int base = 0; base < NN; base += KTILE) {
        __syncthreads();
        for (int m = threadIdx.x; m < KTILE; m += blockDim.x) {
            float px = xb[base + m], py = xb[NN + base + m], pz = xb[2 * NN + base + m];
            pts[m] = make_float4(px, py, pz, fmaf(px, px, fmaf(py, py, pz * pz)));
        }
        __syncthreads();

        for (int g = 0; g < KTILE; g += 32) {
#pragma unroll
            for (int j = 0; j < 32; ++j) {
                float4 p = pts[g + j];
                float v = fmaf(q2x, p.x, fmaf(q2y, p.y, fmaf(q2z, p.z, -p.w)));
                if (v > thr) { bufv[cnt] = v; bufi[cnt] = base + g + j; ++cnt; }
            }
            if (__any_sync(0xffffffffu, cnt >= 32)) {
                int mx = cnt;
#pragma unroll
                for (int o = 16; o; o >>= 1)
                    mx = max(mx, __shfl_xor_sync(0xffffffffu, mx, o));
                for (int q = 0; q < mx; ++q) {
                    float v = (q < cnt) ? bufv[q] : -3.2e38f;
                    int   i = (q < cnt) ? bufi[q] : 0;
                    ins20(v, i, s, si);
                }
                cnt = 0;
                thr = s[19];
            }
        }
    }
    {
        int mx = cnt;
#pragma unroll
        for (int o = 16; o; o >>= 1)
            mx = max(mx, __shfl_xor_sync(0xffffffffu, mx, o));
        for (int q = 0; q < mx; ++q) {
            float v = (q < cnt) ? bufv[q] : -3.2e38f;
            int   i = (q < cnt) ? bufi[q] : 0;
            ins20(v, i, s, si);
        }
    }
    int* op = g_idx + (size_t)(b * NN + n) * KNB;
#pragma unroll
    for (int t = 0; t < 20; ++t) op[t] = si[t];
}

/* ================= feat Gram per-point + fused BN1 finalize ========== */
__global__ void fgram_kernel(const float* __restrict__ x,
                             const float* __restrict__ W1) {
    __shared__ float sm[8][27];
    __shared__ float part[27][8];
    __shared__ float gf[27];
    __shared__ int   isLast;
    const int t = threadIdx.x;
    const int p = blockIdx.x * 256 + t;
    const int b = p >> 12, n = p & (NN - 1);
    const float* xb = x + b * 3 * NN;
    const float cx = xb[n], cy = xb[NN + n], cz = xb[2 * NN + n];
    const int* ip = g_idx + (size_t)p * KNB;

    float s[27];
#pragma unroll
    for (int v = 0; v < 27; ++v) s[v] = 0.f;

#pragma unroll 4
    for (int k = 0; k < KNB; ++k) {
        const int nb = ip[k];
        float f[6];
        f[0] = xb[nb] - cx;
        f[1] = xb[NN + nb] - cy;
        f[2] = xb[2 * NN + nb] - cz;
        f[3] = cx; f[4] = cy; f[5] = cz;
        int u = 0;
#pragma unroll
        for (int i = 0; i < 6; ++i) {
            s[21 + i] += f[i];
#pragma unroll
            for (int j = 0; j <= i; ++j) s[u++] = fmaf(f[i], f[j], s[u]);
        }
    }
#pragma unroll
    for (int off = 16; off; off >>= 1)
#pragma unroll
        for (int v = 0; v < 27; ++v)
            s[v] += __shfl_xor_sync(0xffffffffu, s[v], off);

    if ((t & 31) == 0)
#pragma unroll
        for (int v = 0; v < 27; ++v) sm[t >> 5][v] = s[v];
    __syncthreads();
    if (t < 27) {
        float a = 0.f;
#pragma unroll
        for (int w = 0; w < 8; ++w) a += sm[w][t];
        g_fpart[blockIdx.x * 27 + t] = a;
    }

    __threadfence();
    if (t == 0) isLast = (atomicAdd(&g_cnt0, 1u) == 127u);
    __syncthreads();
    if (!isLast) return;
    if (t == 0) g_cnt0 = 0;

    if (t < 216) {
        int j = t / 8, sl = t % 8;
        float a = 0.f;
        for (int i = sl; i < 128; i += 8) a += g_fpart[i * 27 + j];
        part[j][sl] = a;
    }
    __syncthreads();
    if (t < 27) {
        float a = 0.f;
#pragma unroll
        for (int sl = 0; sl < 8; ++sl) a += part[t][sl];
        gf[t] = a;
    }
    __syncthreads();
    if (t < 64) {
        float w[6];
#pragma unroll
        for (int c = 0; c < 6; ++c) w[c] = W1[t * 6 + c];
        const float invM = 1.f / (float)M1;
        float mu = 0.f;
#pragma unroll
        for (int i = 0; i < 6; ++i) mu = fmaf(w[i], gf[21 + i], mu);
        mu *= invM;
        float q = 0.f;
#pragma unroll
        for (int i = 0; i < 6; ++i)
#pragma unroll
            for (int j = 0; j <= i; ++j) {
                float val = gf[i * (i + 1) / 2 + j];
                float c = w[i] * w[j] * val;
                q += (i == j) ? c : 2.f * c;
            }
        q *= invM;
        g_mu[t] = mu;
        g_rs[t] = rsqrtf(q - mu * mu + EPSB);
    }
}

/* ================= h1 Gram via HMMA hi/lo, 128-edge chunks =========== */
#define HG_ROWB 272
__global__ __launch_bounds__(256) void h1gram_hmma(
        const float* __restrict__ x,  const float* __restrict__ W1,
        const float* __restrict__ g1, const float* __restrict__ b1) {
    __shared__ float f6[2][128][8];
    __shared__ __align__(16) char thi[64 * HG_ROWB];
    __shared__ __align__(16) char tlo[64 * HG_ROWB];
    __shared__ float redc[4][64];
    const int t = threadIdx.x;
    const int w = t >> 5, lane = t & 31;
    const uint32_t uthi = smem_u32(thi), utlo = smem_u32(tlo);
    const int mrow = (w & 3) * 16;
    const int ncol = (w >> 2) * 32;

    const int c  = t & 63;
    const int eg = t >> 6;
    float wr[6];
#pragma unroll
    for (int j = 0; j < 6; ++j) wr[j] = W1[c * 6 + j];
    const float mu = g_mu[c], rsv = g_rs[c], gg = g1[c], bb = b1[c];

    float acc[4][4];
#pragma unroll
    for (int i = 0; i < 4; ++i)
#pragma unroll
        for (int j = 0; j < 4; ++j) acc[i][j] = 0.f;
    float cs = 0.f;

    if (t < 128) {
        int m = blockIdx.x * 1024 + t;
        int p = m / KNB, b_ = p >> 12, n_ = p & (NN - 1);
        const float* xb = x + b_ * 3 * NN;
        int nb = g_idx[m];
        float cx = xb[n_], cy = xb[NN + n_], cz = xb[2 * NN + n_];
        f6[0][t][0] = xb[nb] - cx;
        f6[0][t][1] = xb[NN + nb] - cy;
        f6[0][t][2] = xb[2 * NN + nb] - cz;
        f6[0][t][3] = cx; f6[0][t][4] = cy; f6[0][t][5] = cz;
    }

    for (int cc = 0; cc < 8; ++cc) {
        const int cur = cc & 1;
        __syncthreads();
        if (cc + 1 < 8 && t < 128) {
            int m = blockIdx.x * 1024 + (cc + 1) * 128 + t;
            int p = m / KNB, b_ = p >> 12, n_ = p & (NN - 1);
            const float* xb = x + b_ * 3 * NN;
            int nb = g_idx[m];
            float cx = xb[n_], cy = xb[NN + n_], cz = xb[2 * NN + n_];
            f6[cur ^ 1][t][0] = xb[nb] - cx;
            f6[cur ^ 1][t][1] = xb[NN + nb] - cy;
            f6[cur ^ 1][t][2] = xb[2 * NN + nb] - cz;
            f6[cur ^ 1][t][3] = cx; f6[cur ^ 1][t][4] = cy; f6[cur ^ 1][t][5] = cz;
        }
#pragma unroll 4
        for (int i = 0; i < 32; ++i) {
            const int e = eg + i * 4;
            const float* f = f6[cur][e];
            float y = wr[0] * f[0];
            y = fmaf(wr[1], f[1], y);
            y = fmaf(wr[2], f[2], y);
            y = fmaf(wr[3], f[3], y);
            y = fmaf(wr[4], f[4], y);
            y = fmaf(wr[5], f[5], y);
            float h = fmaxf(fmaf((y - mu) * rsv, gg, bb), 0.f);
            cs += h;
            __nv_bfloat16 hi = __float2bfloat16(h);
            __nv_bfloat16 lo = __float2bfloat16(h - __bfloat162float(hi));
            *(__nv_bfloat16*)(thi + c * HG_ROWB + e * 2) = hi;
            *(__nv_bfloat16*)(tlo + c * HG_ROWB + e * 2) = lo;
        }
        __syncthreads();

#pragma unroll
        for (int ks = 0; ks < 8; ++ks) {
            const uint32_t aoff = (uint32_t)(mrow + (lane & 15)) * HG_ROWB
                                + ((lane >> 4) & 1) * 16 + ks * 32;
            uint32_t ah[4], al[4];
            ldsm_x4(ah, uthi + aoff);
            ldsm_x4(al, utlo + aoff);
#pragma unroll
            for (int nt = 0; nt < 4; ++nt) {
                const uint32_t boff =
                    (uint32_t)(ncol + nt * 8 + (lane & 7)) * HG_ROWB
                    + ((lane >> 3) & 1) * 16 + ks * 32;
                uint32_t bh[2], bl[2];
                ldsm_x2(bh, uthi + boff);
                ldsm_x2(bl, utlo + boff);
                mma_bf16(acc[nt], ah, bh);
                mma_bf16(acc[nt], ah, bl);
                mma_bf16(acc[nt], al, bh);
            }
        }
    }
    redc[eg][c] = cs;
    __syncthreads();
    if (eg == 0)
        g_colpart[(size_t)c * 640 + blockIdx.x] =
            redc[0][c] + redc[1][c] + redc[2][c] + redc[3][c];

    float* gp = g_gpart + (size_t)blockIdx.x * 4096;
    const int r0 = mrow + (lane >> 2);
#pragma unroll
    for (int nt = 0; nt < 4; ++nt) {
        const int c0 = ncol + nt * 8 + (lane & 3) * 2;
        gp[r0 * 64 + c0]           = acc[nt][0];
        gp[r0 * 64 + c0 + 1]       = acc[nt][1];
        gp[(r0 + 8) * 64 + c0]     = acc[nt][2];
        gp[(r0 + 8) * 64 + c0 + 1] = acc[nt][3];
    }
}

/* ================= reduce h1 gram + colsum =========================== */
__global__ void gram2fin_kernel() {
    __shared__ float red[64][4];
    const int t = threadIdx.x;
    const int e = t >> 2, sl = t & 3;
    if (blockIdx.x == 64) {
        float a = 0.f;
        for (int i = sl; i < 640; i += 4) a += g_colpart[(size_t)e * 640 + i];
        red[e][sl] = a;
        __syncthreads();
        if (sl == 0)
            g_h1colsum[e] = red[e][0] + red[e][1] + red[e][2] + red[e][3];
        return;
    }
    const int ge = blockIdx.x * 64 + e;
    float a = 0.f;
    for (int i = sl; i < 640; i += 4) a += g_gpart[(size_t)i * 4096 + ge];
    red[e][sl] = a;
    __syncthreads();
    if (sl == 0)
        g_gram[ge] = red[e][0] + red[e][1] + red[e][2] + red[e][3];
}

/* ================= BN2 stats from h1 Gram ============================ */
__global__ void bn2fin_kernel() {
    const int o = blockIdx.x;
    const int i = threadIdx.x;
    __shared__ float w[64], rq[64], rm[64];
    w[i] = g_w2t[i * 128 + o];
    __syncthreads();
    float qi = 0.f;
    const float* Gi = g_gram + i * 64;
#pragma unroll 8
    for (int j = 0; j < 64; ++j) qi = fmaf(Gi[j], w[j], qi);
    rq[i] = qi * w[i];
    rm[i] = w[i] * g_h1colsum[i];
    __syncthreads();
    for (int s = 32; s > 0; s >>= 1) {
        if (i < s) { rq[i] += rq[i + s]; rm[i] += rm[i + s]; }
        __syncthreads();
    }
    if (i == 0) {
        const float invM = 1.f / (float)M1;
        float mu = rm[0] * invM;
        float var = rq[0] * invM - mu * mu;
        g_mu[64 + o] = mu;
        g_rs[64 + o] = rsqrtf(var + EPSB);
    }
}

/* ================= GEMM2 via mma.sync bf16 hi/lo + x1 & x2 pool ====== */
#define G2_ROWB   144
#define G2_OFF_F6   0
#define G2_OFF_WHI  5120
#define G2_OFF_WLO  (G2_OFF_WHI + 128 * G2_ROWB)
#define G2_OFF_BHI  (G2_OFF_WLO + 128 * G2_ROWB)
#define G2_OFF_BLO  (G2_OFF_BHI + 160 * G2_ROWB)
#define G2_OFF_SLAB (G2_OFF_BLO + 160 * G2_ROWB)
#define G2_SLABW    (16 * 44 * 4)
#define G2_SMEM     (G2_OFF_SLAB + 8 * G2_SLABW)

__global__ __launch_bounds__(256) void gemm2pool_hmma(
        const float* __restrict__ x,  const float* __restrict__ W1,
        const float* __restrict__ g1, const float* __restrict__ b1,
        const float* __restrict__ g2, const float* __restrict__ b2v) {
    extern __shared__ __align__(16) char smem[];
    const int t = threadIdx.x;
    const int w = t >> 5, lane = t & 31;
    const uint32_t sbase = smem_u32(smem);
    float* f6 = (float*)(smem + G2_OFF_F6);

    if (t < 160) {
        int m = blockIdx.x * 160 + t;
        int p = m / KNB, b_ = p >> 12, n_ = p & (NN - 1);
        const float* xb = x + b_ * 3 * NN;
        int nb = g_idx[m];
        float cx = xb[n_], cy = xb[NN + n_], cz = xb[2 * NN + n_];
        f6[t * 8 + 0] = xb[nb] - cx;
        f6[t * 8 + 1] = xb[NN + nb] - cy;
        f6[t * 8 + 2] = xb[2 * NN + nb] - cz;
        f6[t * 8 + 3] = cx; f6[t * 8 + 4] = cy; f6[t * 8 + 5] = cz;
    }
#pragma unroll
    for (int l = 0; l < 4; ++l) {
        int q = t + 256 * l;
        int r = q >> 3, c16 = q & 7;
        *(uint4*)(smem + G2_OFF_WHI + r * G2_ROWB + c16 * 16) = ((const uint4*)g_w2hi)[q];
        *(uint4*)(smem + G2_OFF_WLO + r * G2_ROWB + c16 * 16) = ((const uint4*)g_w2lo)[q];
    }
    __syncthreads();

    {
        const int c  = t & 63;
        const int eg = t >> 6;
        float wr[6];
#pragma unroll
        for (int j = 0; j < 6; ++j) wr[j] = W1[c * 6 + j];
        const float mu = g_mu[c], rsv = g_rs[c], gg = g1[c], bb = b1[c];
#pragma unroll 4
        for (int i = 0; i < 40; ++i) {
            const int e = eg + i * 4;
            const float* f = f6 + e * 8;
            float y = wr[0] * f[0];
            y = fmaf(wr[1], f[1], y);
            y = fmaf(wr[2], f[2], y);
            y = fmaf(wr[3], f[3], y);
            y = fmaf(wr[4], f[4], y);
            y = fmaf(wr[5], f[5], y);
            float h = fmaxf(fmaf((y - mu) * rsv, gg, bb), 0.f);
            __nv_bfloat16 hi = __float2bfloat16(h);
            __nv_bfloat16 lo = __float2bfloat16(h - __bfloat162float(hi));
            *(__nv_bfloat16*)(smem + G2_OFF_BHI + e * G2_ROWB + c * 2) = hi;
            *(__nv_bfloat16*)(smem + G2_OFF_BLO + e * G2_ROWB + c * 2) = lo;
        }
    }
    __syncthreads();

    /* x1 pooling from reconstructed h1 (hi+lo) */
#pragma unroll
    for (int task = t; task < 512; task += 256) {
        const int pl = task >> 6;
        const int c  = task & 63;
        const char* ph = smem + G2_OFF_BHI + c * 2;
        const char* pl2 = smem + G2_OFF_BLO + c * 2;
        float h[20], hmax = 0.f;
#pragma unroll
        for (int k = 0; k < 20; ++k) {
            const int e = pl * 20 + k;
            float hv = __bfloat162float(*(const __nv_bfloat16*)(ph + (size_t)e * G2_ROWB))
                     + __bfloat162float(*(const __nv_bfloat16*)(pl2 + (size_t)e * G2_ROWB));
            h[k] = hv;
            hmax = fmaxf(hmax, hv);
        }
        float se = 0.f, sw = 0.f;
#pragma unroll
        for (int k = 0; k < 20; ++k) {
            float e = __expf(h[k] - hmax);
            se += e;
            sw = fmaf(e, h[k], sw);
        }
        g_cat[(size_t)(blockIdx.x * 8 + pl) * 192 + c] = sw / se;
    }

    const int cbase = w * 16;
    uint32_t ahi[4][4], alo[4][4];
    {
        const uint32_t arow = (uint32_t)(cbase + (lane & 15)) * G2_ROWB
                            + ((lane >> 4) & 1) * 16;
#pragma unroll
        for (int kc = 0; kc < 4; ++kc) {
            ldsm_x4(ahi[kc], sbase + G2_OFF_WHI + arow + kc * 32);
            ldsm_x4(alo[kc], sbase + G2_OFF_WLO + arow + kc * 32);
        }
    }

    const int pch = cbase + (lane & 15);
    const float mu2 = g_mu[64 + pch], rs2 = g_rs[64 + pch];
    const float gg2 = g2[pch], bb2 = b2v[pch];
    float* slab = (float*)(smem + G2_OFF_SLAB + w * G2_SLABW);

#pragma unroll
    for (int grp = 0; grp < 4; ++grp) {
        float D[5][4];
#pragma unroll
        for (int nt = 0; nt < 5; ++nt)
#pragma unroll
            for (int j = 0; j < 4; ++j) D[nt][j] = 0.f;

#pragma unroll
        for (int nt = 0; nt < 5; ++nt) {
            const int ebase = grp * 40 + nt * 8;
            const uint32_t brow = (uint32_t)(ebase + (lane & 7)) * G2_ROWB
                                + ((lane >> 3) & 1) * 16;
#pragma unroll
            for (int kc = 0; kc < 4; ++kc) {
                uint32_t bh[2], bl[2];
                ldsm_x2(bh, sbase + G2_OFF_BHI + brow + kc * 32);
                ldsm_x2(bl, sbase + G2_OFF_BLO + brow + kc * 32);
                mma_bf16(D[nt], ahi[kc], bh);
                mma_bf16(D[nt], ahi[kc], bl);
                mma_bf16(D[nt], alo[kc], bh);
            }
        }
        {
            const int r0 = lane >> 2;
            const int c0 = 2 * (lane & 3);
#pragma unroll
            for (int nt = 0; nt < 5; ++nt) {
                const int col = nt * 8 + c0;
                slab[r0 * 44 + col]           = D[nt][0];
                slab[r0 * 44 + col + 1]       = D[nt][1];
                slab[(r0 + 8) * 44 + col]     = D[nt][2];
                slab[(r0 + 8) * 44 + col + 1] = D[nt][3];
            }
        }
        __syncwarp();
        {
            const int ch = lane & 15;
            const int ph = lane >> 4;
            const float* row = slab + ch * 44 + ph * 20;
            float h[20], hmax = 0.f;
#pragma unroll
            for (int k = 0; k < 20; ++k) {
                float y = row[k];
                h[k] = fmaxf(fmaf((y - mu2) * rs2, gg2, bb2), 0.f);
                hmax = fmaxf(hmax, h[k]);
            }
            float se = 0.f, sw = 0.f;
#pragma unroll
            for (int k = 0; k < 20; ++k) {
                float e = __expf(h[k] - hmax);
                se += e;
                sw = fmaf(e, h[k], sw);
            }
            const int p = blockIdx.x * 8 + grp * 2 + ph;
            g_cat[(size_t)p * 192 + 64 + pch] = sw / se;
        }
        __syncwarp();
    }
}

/* ================= cat Gram (192x192) via HMMA + ldmatrix.trans ====== */
#define CG_ROWB 400
__global__ __launch_bounds__(256) void catgram_trans() {
    __shared__ __align__(16) char thi[32 * CG_ROWB];
    __shared__ __align__(16) char tlo[32 * CG_ROWB];
    const int t = threadIdx.x;
    const int w = t >> 5, lane = t & 31;
    const uint32_t uthi = smem_u32(thi), utlo = smem_u32(tlo);
    const int mrow = (w & 3) * 48;
    const int nch  = blockIdx.y * 64 + (w >> 2) * 32;

    float acc[3][4][4];
#pragma unroll
    for (int mt = 0; mt < 3; ++mt)
#pragma unroll
        for (int nt = 0; nt < 4; ++nt)
#pragma unroll
            for (int j = 0; j < 4; ++j) acc[mt][nt][j] = 0.f;

    for (int cc = 0; cc < 16; ++cc) {
        const int rowbase = blockIdx.x * 512 + cc * 32;
        __syncthreads();
#pragma unroll
        for (int l = 0; l < 6; ++l) {
            int q = t + 256 * l;
            int r = q / 48, cg = q % 48;
            float4 v = *(const float4*)(g_cat + (size_t)(rowbase + r) * 192 + cg * 4);
            uint2 hi, lo;
            split4(v, &hi, &lo);
            *(uint2*)(thi + r * CG_ROWB + cg * 8) = hi;
            *(uint2*)(tlo + r * CG_ROWB + cg * 8) = lo;
        }
        __syncthreads();

#pragma unroll
        for (int ks = 0; ks < 2; ++ks) {
            const int rb = ks * 16;
            uint32_t ah[3][4], al[3][4];
#pragma unroll
            for (int mt = 0; mt < 3; ++mt) {
                const int cb = mrow + mt * 16;
                const uint32_t aoff =
                    (uint32_t)(rb + ((lane >> 4) & 1) * 8 + (lane & 7)) * CG_ROWB
                    + (uint32_t)(cb + ((lane >> 3) & 1) * 8) * 2;
                ldsm_x4_t(ah[mt], uthi + aoff);
                ldsm_x4_t(al[mt], utlo + aoff);
            }
#pragma unroll
            for (int nt = 0; nt < 4; ++nt) {
                const int nb = nch + nt * 8;
                const uint32_t boff =
                    (uint32_t)(rb + ((lane >> 3) & 1) * 8 + (lane & 7)) * CG_ROWB
                    + (uint32_t)nb * 2;
                uint32_t bh[2], bl[2];
                ldsm_x2_t(bh, uthi + boff);
                ldsm_x2_t(bl, utlo + boff);
#pragma unroll
                for (int mt = 0; mt < 3; ++mt) {
                    mma_bf16(acc[mt][nt], ah[mt], bh);
                    mma_bf16(acc[mt][nt], ah[mt], bl);
                    mma_bf16(acc[mt][nt], al[mt], bh);
                }
            }
        }
    }
    float* gp = g_cpart + (size_t)blockIdx.x * 36864;
#pragma unroll
    for (int mt = 0; mt < 3; ++mt) {
        const int r0 = mrow + mt * 16 + (lane >> 2);
#pragma unroll
        for (int nt = 0; nt < 4; ++nt) {
            const int c0 = nch + nt * 8 + (lane & 3) * 2;
            gp[r0 * 192 + c0]             = acc[mt][nt][0];
            gp[r0 * 192 + c0 + 1]         = acc[mt][nt][1];
            gp[(r0 + 8) * 192 + c0]       = acc[mt][nt][2];
            gp[(r0 + 8) * 192 + c0 + 1]   = acc[mt][nt][3];
        }
    }
}

/* ================= cat colsum partials =============================== */
__global__ void catsum_kernel() {
    const int t = threadIdx.x;
    if (t >= 192) return;
    const int r0 = blockIdx.x * 256;
    float a = 0.f;
#pragma unroll 8
    for (int r = 0; r < 256; ++r)
        a += g_cat[(size_t)(r0 + r) * 192 + t];
    g_cspart[t * 128 + blockIdx.x] = a;
}

/* ================= reduce cat gram + colsum ========================== */
__global__ void gram3fin_kernel() {
    const int t = threadIdx.x;
    if (blockIdx.x == 144) {
        if (t < 192) {
            float a = 0.f;
#pragma unroll 8
            for (int p = 0; p < 128; ++p) a += g_cspart[t * 128 + p];
            g_catsum[t] = a;
        }
        return;
    }
    const int e = blockIdx.x * 256 + t;
    float a = 0.f;
#pragma unroll 8
    for (int p = 0; p < 64; ++p) a += g_cpart[(size_t)p * 36864 + e];
    g_cgram[e] = a;
}

/* ================= BN3 stats from cat Gram =========================== */
__global__ void bn3fin_kernel() {
    const int o = blockIdx.x;
    const int i = threadIdx.x;
    __shared__ float w[192], rq[192], rm[192];
    w[i] = g_w3t[i * 256 + o];
    __syncthreads();
    float qi = 0.f;
    const float* Gi = g_cgram + i * 192;
#pragma unroll 8
    for (int j = 0; j < 192; ++j) qi = fmaf(Gi[j], w[j], qi);
    rq[i] = qi * w[i];
    rm[i] = w[i] * g_catsum[i];
    __syncthreads();
    for (int s = 96; s >= 3; s >>= 1) {
        if (i < s) { rq[i] += rq[i + s]; rm[i] += rm[i + s]; }
        __syncthreads();
    }
    if (i == 0) {
        const float invN = 1.f / (float)NPTS;
        float mu = (rm[0] + rm[1] + rm[2]) * invN;
        float var = (rq[0] + rq[1] + rq[2]) * invN - mu * mu;
        g_mu[192 + o] = mu;
        g_rs[192 + o] = rsqrtf(var + EPSB);
    }
}

/* ================= GEMM3 via HMMA hi/lo + BN3 + transposed out ======= */
#define G3_ROWB 144
#define G3_OFF_AHI 0
#define G3_OFF_ALO (G3_OFF_AHI + 128 * G3_ROWB)
#define G3_OFF_BHI (G3_OFF_ALO + 128 * G3_ROWB)
#define G3_OFF_BLO (G3_OFF_BHI + 128 * G3_ROWB)
#define G3_SMEM    (G3_OFF_BLO + 128 * G3_ROWB)

__global__ __launch_bounds__(256) void gemm3out_hmma(
        const float* __restrict__ g3, const float* __restrict__ b3,
        float* __restrict__ out) {
    extern __shared__ __align__(16) char smem[];
    const int t = threadIdx.x;
    const int w = t >> 5, lane = t & 31;
    const uint32_t sbase = smem_u32(smem);
    const int mbase = blockIdx.x * 128;
    const int nbase = blockIdx.y * 128;
    const int mrow = (w & 3) * 32;
    const int ncol = (w >> 2) * 64;

    float acc[2][8][4];
#pragma unroll
    for (int mt = 0; mt < 2; ++mt)
#pragma unroll
        for (int nt = 0; nt < 8; ++nt)
#pragma unroll
            for (int j = 0; j < 4; ++j) acc[mt][nt][j] = 0.f;

#pragma unroll
    for (int kc = 0; kc < 3; ++kc) {
#pragma unroll
        for (int l = 0; l < 8; ++l) {
            int q = t + 256 * l;
            int r = q >> 4, kq = (q & 15) * 4;
            float4 v = *(const float4*)(g_cat + (size_t)(mbase + r) * 192
                                        + kc * 64 + kq);
            uint2 hi, lo;
            split4(v, &hi, &lo);
            *(uint2*)(smem + G3_OFF_AHI + r * G3_ROWB + kq * 2) = hi;
            *(uint2*)(smem + G3_OFF_ALO + r * G3_ROWB + kq * 2) = lo;
        }
#pragma unroll
        for (int l = 0; l < 4; ++l) {
            int q = t + 256 * l;
            int r = q >> 3, c16 = q & 7;
            const char* srch = (const char*)g_w3hi
                + (size_t)(nbase + r) * 384 + kc * 128 + c16 * 16;
            const char* srcl = (const char*)g_w3lo
                + (size_t)(nbase + r) * 384 + kc * 128 + c16 * 16;
            *(uint4*)(smem + G3_OFF_BHI + r * G3_ROWB + c16 * 16) = *(const uint4*)srch;
            *(uint4*)(smem + G3_OFF_BLO + r * G3_ROWB + c16 * 16) = *(const uint4*)srcl;
        }
        __syncthreads();

#pragma unroll
        for (int ks = 0; ks < 4; ++ks) {
            uint32_t ah[2][4], al[2][4];
#pragma unroll
            for (int mt = 0; mt < 2; ++mt) {
                const uint32_t aoff =
                    (uint32_t)(mrow + mt * 16 + (lane & 15)) * G3_ROWB
                    + ((lane >> 4) & 1) * 16 + ks * 32;
                ldsm_x4(ah[mt], sbase + G3_OFF_AHI + aoff);
                ldsm_x4(al[mt], sbase + G3_OFF_ALO + aoff);
            }
#pragma unroll
            for (int nt = 0; nt < 8; ++nt) {
                const uint32_t boff =
                    (uint32_t)(ncol + nt * 8 + (lane & 7)) * G3_ROWB
                    + ((lane >> 3) & 1) * 16 + ks * 32;
                uint32_t bh[2], bl[2];
                ldsm_x2(bh, sbase + G3_OFF_BHI + boff);
                ldsm_x2(bl, sbase + G3_OFF_BLO + boff);
#pragma unroll
                for (int mt = 0; mt < 2; ++mt) {
                    mma_bf16(acc[mt][nt], ah[mt], bh);
                    mma_bf16(acc[mt][nt], ah[mt], bl);
                    mma_bf16(acc[mt][nt], al[mt], bh);
                }
            }
        }
        __syncthreads();
    }

    float* slab = (float*)smem;
#pragma unroll
    for (int mt = 0; mt < 2; ++mt) {
        const int r = mrow + mt * 16 + (lane >> 2);
#pragma unroll
        for (int nt = 0; nt < 8; ++nt) {
            const int cl = ncol + nt * 8 + (lane & 3) * 2;
            slab[cl * 132 + r]           = acc[mt][nt][0];
            slab[(cl + 1) * 132 + r]     = acc[mt][nt][1];
            slab[cl * 132 + r + 8]       = acc[mt][nt][2];
            slab[(cl + 1) * 132 + r + 8] = acc[mt][nt][3];
        }
    }
    __syncthreads();

    const int b = mbase >> 12;
    const int nloc = mbase & (NN - 1);
    const int cl = t >> 1;
    const int half = t & 1;
    const int o = nbase + cl;
    const float mu = g_mu[192 + o], rsv = g_rs[192 + o];
    const float gg = g3[o], bb = b3[o];
    const float* srow = slab + cl * 132 + half * 64;
    float* op = out + ((size_t)b * 256 + o) * NN + nloc + half * 64;
#pragma unroll
    for (int j = 0; j < 16; ++j) {
        float4 v = *(const float4*)(srow + j * 4);
        float4 r;
        r.x = fmaxf(fmaf((v.x - mu) * rsv, gg, bb), 0.f);
        r.y = fmaxf(fmaf((v.y - mu) * rsv, gg, bb), 0.f);
        r.z = fmaxf(fmaf((v.z - mu) * rsv, gg, bb), 0.f);
        r.w = fmaxf(fmaf((v.w - mu) * rsv, gg, bb), 0.f);
        *(float4*)(op + j * 4) = r;
    }
}

/* ================= launcher ========================================== */
extern "C" void kernel_launch(void* const* d_in, const int* in_sizes, int n_in,
                              void* d_out, int out_size) {
    const float* x  = (const float*)d_in[0];
    const float* W1 = (const float*)d_in[1];
    const float* g1 = (const float*)d_in[2];
    const float* b1 = (const float*)d_in[3];
    const float* W2 = (const float*)d_in[4];
    const float* g2 = (const float*)d_in[5];
    const float* b2 = (const float*)d_in[6];
    const float* W3 = (const float*)d_in[7];
    const float* g3 = (const float*)d_in[8];
    const float* b3 = (const float*)d_in[9];
    float* out = (float*)d_out;

    cudaFuncSetAttribute(gemm2pool_hmma,
                         cudaFuncAttributeMaxDynamicSharedMemorySize, G2_SMEM);
    cudaFuncSetAttribute(gemm3out_hmma,
                         cudaFuncAttributeMaxDynamicSharedMemorySize, G3_SMEM);

    prep_kernel<<<192, 256>>>(W2, W3);
    knn_kernel<<<dim3(BB, NN / 256), 256>>>(x);

    fgram_kernel<<<128, 256>>>(x, W1);           /* + BN1 finalize */

    h1gram_hmma<<<640, 256>>>(x, W1, g1, b1);    /* profiled slot  */
    gram2fin_kernel<<<65, 256>>>();
    bn2fin_kernel<<<128, 64>>>();

    gemm2pool_hmma<<<M1 / 160, 256, G2_SMEM>>>(x, W1, g1, b1, g2, b2);

    catgram_trans<<<dim3(64, 3), 256>>>();
    catsum_kernel<<<128, 256>>>();
    gram3fin_kernel<<<145, 256>>>();
    bn3fin_kernel<<<256, 192>>>();

    gemm3out_hmma<<<dim3(NPTS / 128, 2), 256, G3_SMEM>>>(g3, b3, out);

    (void)in_sizes; (void)n_in; (void)out_size;
}

// round 17
// speedup vs baseline: 1.1993x; 1.0351x over previous
#include <cuda_runtime.h>
#include <cuda_bf16.h>
#include <cstdint>

#define BB    8
#define NN    4096
#define KNB   20
#define NPTS  (BB * NN)          /* 32768  */
#define M1    (NPTS * KNB)       /* 655360 */
#define EPSB  1e-5f

/* ================= static device scratch (no allocations) ============= */
__device__ int   g_idx[M1];                         /* knn indices          */
__device__ float g_cat[(size_t)NPTS * 192];         /* [x1|x2] [P,192]      */
__device__ float g_w2t[64 * 128];                   /* W2^T [k][o]          */
__device__ float g_w3t[192 * 256];                  /* W3^T [k][o]          */
__device__ __nv_bfloat16 g_w2hi[128 * 64];          /* W2 bf16 hi [o][k]    */
__device__ __nv_bfloat16 g_w2lo[128 * 64];          /* W2 bf16 lo [o][k]    */
__device__ __nv_bfloat16 g_w3hi[256 * 192];         /* W3 bf16 hi [o][k]    */
__device__ __nv_bfloat16 g_w3lo[256 * 192];         /* W3 bf16 lo [o][k]    */
__device__ float g_fpart[128 * 27];                 /* feat gram partials   */
__device__ float g_colpart[64 * 640];               /* h1 colsum partials   */
__device__ float g_gpart[(size_t)640 * 4096];       /* h1 gram partials     */
__device__ float g_gram[4096];                      /* h1 gram 64x64        */
__device__ float g_h1colsum[64];
__device__ float g_cpart[(size_t)64 * 36864];       /* cat gram partials    */
__device__ float g_cspart[192 * 128];               /* cat colsum partials  */
__device__ float g_cgram[36864];                    /* cat gram 192x192     */
__device__ float g_catsum[192];
__device__ float g_mu[448];                         /* L1:0 L2:64 L3:192    */
__device__ float g_rs[448];
__device__ unsigned int g_cnt0;                     /* fgram counter        */

/* ================= mma.sync / ldmatrix helpers (plain PTX ISA) ======= */
__device__ __forceinline__ uint32_t smem_u32(const void* p) {
    uint32_t a;
    asm("{ .reg .u64 t; cvta.to.shared.u64 t, %1; cvt.u32.u64 %0, t; }"
        : "=r"(a) : "l"(p));
    return a;
}
__device__ __forceinline__ void ldsm_x4(uint32_t* r, uint32_t addr) {
    asm volatile("ldmatrix.sync.aligned.m8n8.x4.shared.b16 {%0,%1,%2,%3}, [%4];"
                 : "=r"(r[0]), "=r"(r[1]), "=r"(r[2]), "=r"(r[3]) : "r"(addr));
}
__device__ __forceinline__ void ldsm_x2(uint32_t* r, uint32_t addr) {
    asm volatile("ldmatrix.sync.aligned.m8n8.x2.shared.b16 {%0,%1}, [%2];"
                 : "=r"(r[0]), "=r"(r[1]) : "r"(addr));
}
__device__ __forceinline__ void ldsm_x4_t(uint32_t* r, uint32_t addr) {
    asm volatile("ldmatrix.sync.aligned.m8n8.x4.trans.shared.b16 {%0,%1,%2,%3}, [%4];"
                 : "=r"(r[0]), "=r"(r[1]), "=r"(r[2]), "=r"(r[3]) : "r"(addr));
}
__device__ __forceinline__ void ldsm_x2_t(uint32_t* r, uint32_t addr) {
    asm volatile("ldmatrix.sync.aligned.m8n8.x2.trans.shared.b16 {%0,%1}, [%2];"
                 : "=r"(r[0]), "=r"(r[1]) : "r"(addr));
}
__device__ __forceinline__ void mma_bf16(float* d, const uint32_t* a,
                                         const uint32_t* b) {
    asm volatile(
        "mma.sync.aligned.m16n8k16.row.col.f32.bf16.bf16.f32 "
        "{%0,%1,%2,%3}, {%4,%5,%6,%7}, {%8,%9}, {%0,%1,%2,%3};"
        : "+f"(d[0]), "+f"(d[1]), "+f"(d[2]), "+f"(d[3])
        : "r"(a[0]), "r"(a[1]), "r"(a[2]), "r"(a[3]), "r"(b[0]), "r"(b[1]));
}
__device__ __forceinline__ void split4(float4 v, uint2* hi, uint2* lo) {
    __nv_bfloat16 hx = __float2bfloat16(v.x), hy = __float2bfloat16(v.y);
    __nv_bfloat16 hz = __float2bfloat16(v.z), hw = __float2bfloat16(v.w);
    __nv_bfloat16 lx = __float2bfloat16(v.x - __bfloat162float(hx));
    __nv_bfloat16 ly = __float2bfloat16(v.y - __bfloat162float(hy));
    __nv_bfloat16 lz = __float2bfloat16(v.z - __bfloat162float(hz));
    __nv_bfloat16 lw = __float2bfloat16(v.w - __bfloat162float(hw));
    __nv_bfloat162 h01, h23, l01, l23;
    h01.x = hx; h01.y = hy; h23.x = hz; h23.y = hw;
    l01.x = lx; l01.y = ly; l23.x = lz; l23.y = lw;
    hi->x = *(uint32_t*)&h01; hi->y = *(uint32_t*)&h23;
    lo->x = *(uint32_t*)&l01; lo->y = *(uint32_t*)&l23;
}

/* ================= prep: transposes + bf16 splits ==================== */
__global__ void prep_kernel(const float* __restrict__ W2,
                            const float* __restrict__ W3) {
    int t = blockIdx.x * blockDim.x + threadIdx.x;
    if (t < 64 * 128) {
        int k = t / 128, o = t % 128;
        g_w2t[t] = W2[o * 64 + k];
        float w = W2[t];
        __nv_bfloat16 hi = __float2bfloat16(w);
        g_w2hi[t] = hi;
        g_w2lo[t] = __float2bfloat16(w - __bfloat162float(hi));
    }
    if (t < 192 * 256) {
        int k = t / 256, o = t % 256;
        g_w3t[t] = W3[o * 192 + k];
        float w = W3[t];
        __nv_bfloat16 hi = __float2bfloat16(w);
        g_w3hi[t] = hi;
        g_w3lo[t] = __float2bfloat16(w - __bfloat162float(hi));
    }
}

/* ================= kNN: branch-light buffered top-20 ================= */
#define KTILE 1024
#define BUFSZ 64

__device__ __forceinline__ void ins20(float v, int id, float* s, int* si) {
    bool c[20];
#pragma unroll
    for (int t = 0; t < 20; ++t) c[t] = v > s[t];
#pragma unroll
    for (int t = 19; t >= 1; --t) {
        float nv = c[t - 1] ? s[t - 1] : v;
        int   ni = c[t - 1] ? si[t - 1] : id;
        s[t]  = c[t] ? nv : s[t];
        si[t] = c[t] ? ni : si[t];
    }
    s[0]  = c[0] ? v : s[0];
    si[0] = c[0] ? id : si[0];
}

__global__ void knn_kernel(const float* __restrict__ x) {
    __shared__ float4 pts[KTILE];
    const int b = blockIdx.x;
    const int n = blockIdx.y * blockDim.x + threadIdx.x;
    const float* xb = x + b * 3 * NN;
    const float qx = xb[n], qy = xb[NN + n], qz = xb[2 * NN + n];
    const float q2x = 2.f * qx, q2y = 2.f * qy, q2z = 2.f * qz;

    float s[20];
    int   si[20];
#pragma unroll
    for (int t = 0; t < 20; ++t) { s[t] = -3.0e38f; si[t] = 0; }
    float thr = -3.0e38f;

    float bufv[BUFSZ];
    int   bufi[BUFSZ];
    int   cnt = 0;

    for (int base = 0; base < NN; base += KTILE) {
        __syncthreads();
        for (int m = threadIdx.x; m < KTILE; m += blockDim.x) {
            float px = xb[base + m], py = xb[NN + base + m], pz = xb[2 * NN + base + m];
            pts[m] = make_float4(px, py, pz, fmaf(px, px, fmaf(py, py, pz * pz)));
        }
        __syncthreads();

        for (int g = 0; g < KTILE; g += 32) {
#pragma unroll
            for (int j = 0; j < 32; ++j) {
                float4 p = pts[g + j];
                float v = fmaf(q2x, p.x, fmaf(q2y, p.y, fmaf(q2z, p.z, -p.w)));
                if (v > thr) { bufv[cnt] = v; bufi[cnt] = base + g + j; ++cnt; }
            }
            if (__any_sync(0xffffffffu, cnt >= 32)) {
                int mx = cnt;
#pragma unroll
                for (int o = 16; o; o >>= 1)
                    mx = max(mx, __shfl_xor_sync(0xffffffffu, mx, o));
                for (int q = 0; q < mx; ++q) {
                    float v = (q < cnt) ? bufv[q] : -3.2e38f;
                    int   i = (q < cnt) ? bufi[q] : 0;
                    ins20(v, i, s, si);
                }
                cnt = 0;
                thr = s[19];
            }
        }
    }
    {
        int mx = cnt;
#pragma unroll
        for (int o = 16; o; o >>= 1)
            mx = max(mx, __shfl_xor_sync(0xffffffffu, mx, o));
        for (int q = 0; q < mx; ++q) {
            float v = (q < cnt) ? bufv[q] : -3.2e38f;
            int   i = (q < cnt) ? bufi[q] : 0;
            ins20(v, i, s, si);
        }
    }
    int* op = g_idx + (size_t)(b * NN + n) * KNB;
#pragma unroll
    for (int t = 0; t < 20; ++t) op[t] = si[t];
}

/* ================= feat Gram per-point + fused BN1 finalize ========== */
__global__ void fgram_kernel(const float* __restrict__ x,
                             const float* __restrict__ W1) {
    __shared__ float sm[8][27];
    __shared__ float part[27][8];
    __shared__ float gf[27];
    __shared__ int   isLast;
    const int t = threadIdx.x;
    const int p = blockIdx.x * 256 + t;
    const int b = p >> 12, n = p & (NN - 1);
    const float* xb = x + b * 3 * NN;
    const float cx = xb[n], cy = xb[NN + n], cz = xb[2 * NN + n];
    const int* ip = g_idx + (size_t)p * KNB;

    float s[27];
#pragma unroll
    for (int v = 0; v < 27; ++v) s[v] = 0.f;

#pragma unroll 4
    for (int k = 0; k < KNB; ++k) {
        const int nb = ip[k];
        float f[6];
        f[0] = xb[nb] - cx;
        f[1] = xb[NN + nb] - cy;
        f[2] = xb[2 * NN + nb] - cz;
        f[3] = cx; f[4] = cy; f[5] = cz;
        int u = 0;
#pragma unroll
        for (int i = 0; i < 6; ++i) {
            s[21 + i] += f[i];
#pragma unroll
            for (int j = 0; j <= i; ++j) s[u++] = fmaf(f[i], f[j], s[u]);
        }
    }
#pragma unroll
    for (int off = 16; off; off >>= 1)
#pragma unroll
        for (int v = 0; v < 27; ++v)
            s[v] += __shfl_xor_sync(0xffffffffu, s[v], off);

    if ((t & 31) == 0)
#pragma unroll
        for (int v = 0; v < 27; ++v) sm[t >> 5][v] = s[v];
    __syncthreads();
    if (t < 27) {
        float a = 0.f;
#pragma unroll
        for (int w = 0; w < 8; ++w) a += sm[w][t];
        g_fpart[blockIdx.x * 27 + t] = a;
    }

    __threadfence();
    if (t == 0) isLast = (atomicAdd(&g_cnt0, 1u) == 127u);
    __syncthreads();
    if (!isLast) return;
    if (t == 0) g_cnt0 = 0;

    if (t < 216) {
        int j = t / 8, sl = t % 8;
        float a = 0.f;
        for (int i = sl; i < 128; i += 8) a += g_fpart[i * 27 + j];
        part[j][sl] = a;
    }
    __syncthreads();
    if (t < 27) {
        float a = 0.f;
#pragma unroll
        for (int sl = 0; sl < 8; ++sl) a += part[t][sl];
        gf[t] = a;
    }
    __syncthreads();
    if (t < 64) {
        float w[6];
#pragma unroll
        for (int c = 0; c < 6; ++c) w[c] = W1[t * 6 + c];
        const float invM = 1.f / (float)M1;
        float mu = 0.f;
#pragma unroll
        for (int i = 0; i < 6; ++i) mu = fmaf(w[i], gf[21 + i], mu);
        mu *= invM;
        float q = 0.f;
#pragma unroll
        for (int i = 0; i < 6; ++i)
#pragma unroll
            for (int j = 0; j <= i; ++j) {
                float val = gf[i * (i + 1) / 2 + j];
                float c = w[i] * w[j] * val;
                q += (i == j) ? c : 2.f * c;
            }
        q *= invM;
        g_mu[t] = mu;
        g_rs[t] = rsqrtf(q - mu * mu + EPSB);
    }
}

/* ================= h1 Gram via HMMA hi/lo, x4 B-loads ================ */
#define HG_ROWB 272
__global__ __launch_bounds__(256) void h1gram_hmma(
        const float* __restrict__ x,  const float* __restrict__ W1,
        const float* __restrict__ g1, const float* __restrict__ b1) {
    __shared__ float f6[2][128][8];
    __shared__ __align__(16) char thi[64 * HG_ROWB];
    __shared__ __align__(16) char tlo[64 * HG_ROWB];
    __shared__ float redc[4][64];
    const int t = threadIdx.x;
    const int w = t >> 5, lane = t & 31;
    const uint32_t uthi = smem_u32(thi), utlo = smem_u32(tlo);
    const int mrow = (w & 3) * 16;
    const int ncol = (w >> 2) * 32;

    const int c  = t & 63;
    const int eg = t >> 6;
    float wr[6];
#pragma unroll
    for (int j = 0; j < 6; ++j) wr[j] = W1[c * 6 + j];
    const float mu = g_mu[c], rsv = g_rs[c], gg = g1[c], bb = b1[c];

    float acc[4][4];
#pragma unroll
    for (int i = 0; i < 4; ++i)
#pragma unroll
        for (int j = 0; j < 4; ++j) acc[i][j] = 0.f;
    float cs = 0.f;

    if (t < 128) {
        int m = blockIdx.x * 1024 + t;
        int p = m / KNB, b_ = p >> 12, n_ = p & (NN - 1);
        const float* xb = x + b_ * 3 * NN;
        int nb = g_idx[m];
        float cx = xb[n_], cy = xb[NN + n_], cz = xb[2 * NN + n_];
        f6[0][t][0] = xb[nb] - cx;
        f6[0][t][1] = xb[NN + nb] - cy;
        f6[0][t][2] = xb[2 * NN + nb] - cz;
        f6[0][t][3] = cx; f6[0][t][4] = cy; f6[0][t][5] = cz;
    }

    for (int cc = 0; cc < 8; ++cc) {
        const int cur = cc & 1;
        __syncthreads();
        if (cc + 1 < 8 && t < 128) {
            int m = blockIdx.x * 1024 + (cc + 1) * 128 + t;
            int p = m / KNB, b_ = p >> 12, n_ = p & (NN - 1);
            const float* xb = x + b_ * 3 * NN;
            int nb = g_idx[m];
            float cx = xb[n_], cy = xb[NN + n_], cz = xb[2 * NN + n_];
            f6[cur ^ 1][t][0] = xb[nb] - cx;
            f6[cur ^ 1][t][1] = xb[NN + nb] - cy;
            f6[cur ^ 1][t][2] = xb[2 * NN + nb] - cz;
            f6[cur ^ 1][t][3] = cx; f6[cur ^ 1][t][4] = cy; f6[cur ^ 1][t][5] = cz;
        }
        /* fill: pairs (e, e+1), one 32-bit store per tile */
#pragma unroll 4
        for (int i = 0; i < 16; ++i) {
            const int e = 2 * eg + 8 * i;
            const float* f0 = f6[cur][e];
            const float* f1 = f6[cur][e + 1];
            float y0 = wr[0] * f0[0];
            y0 = fmaf(wr[1], f0[1], y0);
            y0 = fmaf(wr[2], f0[2], y0);
            y0 = fmaf(wr[3], f0[3], y0);
            y0 = fmaf(wr[4], f0[4], y0);
            y0 = fmaf(wr[5], f0[5], y0);
            float y1 = wr[0] * f1[0];
            y1 = fmaf(wr[1], f1[1], y1);
            y1 = fmaf(wr[2], f1[2], y1);
            y1 = fmaf(wr[3], f1[3], y1);
            y1 = fmaf(wr[4], f1[4], y1);
            y1 = fmaf(wr[5], f1[5], y1);
            float h0 = fmaxf(fmaf((y0 - mu) * rsv, gg, bb), 0.f);
            float h1 = fmaxf(fmaf((y1 - mu) * rsv, gg, bb), 0.f);
            cs += h0 + h1;
            __nv_bfloat16 h0h = __float2bfloat16(h0);
            __nv_bfloat16 h1h = __float2bfloat16(h1);
            __nv_bfloat162 ph, pl;
            ph.x = h0h; ph.y = h1h;
            pl.x = __float2bfloat16(h0 - __bfloat162float(h0h));
            pl.y = __float2bfloat16(h1 - __bfloat162float(h1h));
            *(uint32_t*)(thi + c * HG_ROWB + e * 2) = *(uint32_t*)&ph;
            *(uint32_t*)(tlo + c * HG_ROWB + e * 2) = *(uint32_t*)&pl;
        }
        __syncthreads();

#pragma unroll
        for (int ks = 0; ks < 8; ++ks) {
            const uint32_t aoff = (uint32_t)(mrow + (lane & 15)) * HG_ROWB
                                + ((lane >> 4) & 1) * 16 + ks * 32;
            uint32_t ah[4], al[4];
            ldsm_x4(ah, uthi + aoff);
            ldsm_x4(al, utlo + aoff);
#pragma unroll
            for (int ntp = 0; ntp < 2; ++ntp) {
                /* x4 B: matrices = {nt,k0},{nt,k1},{nt+1,k0},{nt+1,k1} */
                const uint32_t brow = (uint32_t)(ncol + ntp * 16
                                     + ((lane >> 4) & 1) * 8 + (lane & 7));
                const uint32_t boff = brow * HG_ROWB
                                     + ((lane >> 3) & 1) * 16 + ks * 32;
                uint32_t bh[4], bl[4];
                ldsm_x4(bh, uthi + boff);
                ldsm_x4(bl, utlo + boff);
                mma_bf16(acc[2 * ntp],     ah, bh);
                mma_bf16(acc[2 * ntp],     ah, bl);
                mma_bf16(acc[2 * ntp],     al, bh);
                mma_bf16(acc[2 * ntp + 1], ah, bh + 2);
                mma_bf16(acc[2 * ntp + 1], ah, bl + 2);
                mma_bf16(acc[2 * ntp + 1], al, bh + 2);
            }
        }
    }
    redc[eg][c] = cs;
    __syncthreads();
    if (eg == 0)
        g_colpart[(size_t)c * 640 + blockIdx.x] =
            redc[0][c] + redc[1][c] + redc[2][c] + redc[3][c];

    float* gp = g_gpart + (size_t)blockIdx.x * 4096;
    const int r0 = mrow + (lane >> 2);
#pragma unroll
    for (int nt = 0; nt < 4; ++nt) {
        const int c0 = ncol + nt * 8 + (lane & 3) * 2;
        gp[r0 * 64 + c0]           = acc[nt][0];
        gp[r0 * 64 + c0 + 1]       = acc[nt][1];
        gp[(r0 + 8) * 64 + c0]     = acc[nt][2];
        gp[(r0 + 8) * 64 + c0 + 1] = acc[nt][3];
    }
}

/* ================= reduce h1 gram + colsum =========================== */
__global__ void gram2fin_kernel() {
    __shared__ float red[64][4];
    const int t = threadIdx.x;
    const int e = t >> 2, sl = t & 3;
    if (blockIdx.x == 64) {
        float a = 0.f;
        for (int i = sl; i < 640; i += 4) a += g_colpart[(size_t)e * 640 + i];
        red[e][sl] = a;
        __syncthreads();
        if (sl == 0)
            g_h1colsum[e] = red[e][0] + red[e][1] + red[e][2] + red[e][3];
        return;
    }
    const int ge = blockIdx.x * 64 + e;
    float a = 0.f;
    for (int i = sl; i < 640; i += 4) a += g_gpart[(size_t)i * 4096 + ge];
    red[e][sl] = a;
    __syncthreads();
    if (sl == 0)
        g_gram[ge] = red[e][0] + red[e][1] + red[e][2] + red[e][3];
}

/* ================= BN2 stats from h1 Gram ============================ */
__global__ void bn2fin_kernel() {
    const int o = blockIdx.x;
    const int i = threadIdx.x;
    __shared__ float w[64], rq[64], rm[64];
    w[i] = g_w2t[i * 128 + o];
    __syncthreads();
    float qi = 0.f;
    const float* Gi = g_gram + i * 64;
#pragma unroll 8
    for (int j = 0; j < 64; ++j) qi = fmaf(Gi[j], w[j], qi);
    rq[i] = qi * w[i];
    rm[i] = w[i] * g_h1colsum[i];
    __syncthreads();
    for (int s = 32; s > 0; s >>= 1) {
        if (i < s) { rq[i] += rq[i + s]; rm[i] += rm[i + s]; }
        __syncthreads();
    }
    if (i == 0) {
        const float invM = 1.f / (float)M1;
        float mu = rm[0] * invM;
        float var = rq[0] * invM - mu * mu;
        g_mu[64 + o] = mu;
        g_rs[64 + o] = rsqrtf(var + EPSB);
    }
}

/* ================= GEMM2 via mma.sync bf16 hi/lo + x1 & x2 pool ====== */
#define G2_ROWB   144
#define G2_OFF_F6   0
#define G2_OFF_WHI  5120
#define G2_OFF_WLO  (G2_OFF_WHI + 128 * G2_ROWB)
#define G2_OFF_BHI  (G2_OFF_WLO + 128 * G2_ROWB)
#define G2_OFF_BLO  (G2_OFF_BHI + 160 * G2_ROWB)
#define G2_OFF_SLAB (G2_OFF_BLO + 160 * G2_ROWB)
#define G2_SLABW    (16 * 44 * 4)
#define G2_SMEM     (G2_OFF_SLAB + 8 * G2_SLABW)

__global__ __launch_bounds__(256) void gemm2pool_hmma(
        const float* __restrict__ x,  const float* __restrict__ W1,
        const float* __restrict__ g1, const float* __restrict__ b1,
        const float* __restrict__ g2, const float* __restrict__ b2v) {
    extern __shared__ __align__(16) char smem[];
    const int t = threadIdx.x;
    const int w = t >> 5, lane = t & 31;
    const uint32_t sbase = smem_u32(smem);
    float* f6 = (float*)(smem + G2_OFF_F6);

    if (t < 160) {
        int m = blockIdx.x * 160 + t;
        int p = m / KNB, b_ = p >> 12, n_ = p & (NN - 1);
        const float* xb = x + b_ * 3 * NN;
        int nb = g_idx[m];
        float cx = xb[n_], cy = xb[NN + n_], cz = xb[2 * NN + n_];
        f6[t * 8 + 0] = xb[nb] - cx;
        f6[t * 8 + 1] = xb[NN + nb] - cy;
        f6[t * 8 + 2] = xb[2 * NN + nb] - cz;
        f6[t * 8 + 3] = cx; f6[t * 8 + 4] = cy; f6[t * 8 + 5] = cz;
    }
#pragma unroll
    for (int l = 0; l < 4; ++l) {
        int q = t + 256 * l;
        int r = q >> 3, c16 = q & 7;
        *(uint4*)(smem + G2_OFF_WHI + r * G2_ROWB + c16 * 16) = ((const uint4*)g_w2hi)[q];
        *(uint4*)(smem + G2_OFF_WLO + r * G2_ROWB + c16 * 16) = ((const uint4*)g_w2lo)[q];
    }
    __syncthreads();

    {
        const int c  = t & 63;
        const int eg = t >> 6;
        float wr[6];
#pragma unroll
        for (int j = 0; j < 6; ++j) wr[j] = W1[c * 6 + j];
        const float mu = g_mu[c], rsv = g_rs[c], gg = g1[c], bb = b1[c];
#pragma unroll 4
        for (int i = 0; i < 40; ++i) {
            const int e = eg + i * 4;
            const float* f = f6 + e * 8;
            float y = wr[0] * f[0];
            y = fmaf(wr[1], f[1], y);
            y = fmaf(wr[2], f[2], y);
            y = fmaf(wr[3], f[3], y);
            y = fmaf(wr[4], f[4], y);
            y = fmaf(wr[5], f[5], y);
            float h = fmaxf(fmaf((y - mu) * rsv, gg, bb), 0.f);
            __nv_bfloat16 hi = __float2bfloat16(h);
            __nv_bfloat16 lo = __float2bfloat16(h - __bfloat162float(hi));
            *(__nv_bfloat16*)(smem + G2_OFF_BHI + e * G2_ROWB + c * 2) = hi;
            *(__nv_bfloat16*)(smem + G2_OFF_BLO + e * G2_ROWB + c * 2) = lo;
        }
    }
    __syncthreads();

    /* x1 pooling from reconstructed h1 (hi+lo) */
#pragma unroll
    for (int task = t; task < 512; task += 256) {
        const int pl = task >> 6;
        const int c  = task & 63;
        const char* ph = smem + G2_OFF_BHI + c * 2;
        const char* pl2 = smem + G2_OFF_BLO + c * 2;
        float h[20], hmax = 0.f;
#pragma unroll
        for (int k = 0; k < 20; ++k) {
            const int e = pl * 20 + k;
            float hv = __bfloat162float(*(const __nv_bfloat16*)(ph + (size_t)e * G2_ROWB))
                     + __bfloat162float(*(const __nv_bfloat16*)(pl2 + (size_t)e * G2_ROWB));
            h[k] = hv;
            hmax = fmaxf(hmax, hv);
        }
        float se = 0.f, sw = 0.f;
#pragma unroll
        for (int k = 0; k < 20; ++k) {
            float e = __expf(h[k] - hmax);
            se += e;
            sw = fmaf(e, h[k], sw);
        }
        g_cat[(size_t)(blockIdx.x * 8 + pl) * 192 + c] = sw / se;
    }

    const int cbase = w * 16;
    uint32_t ahi[4][4], alo[4][4];
    {
        const uint32_t arow = (uint32_t)(cbase + (lane & 15)) * G2_ROWB
                            + ((lane >> 4) & 1) * 16;
#pragma unroll
        for (int kc = 0; kc < 4; ++kc) {
            ldsm_x4(ahi[kc], sbase + G2_OFF_WHI + arow + kc * 32);
            ldsm_x4(alo[kc], sbase + G2_OFF_WLO + arow + kc * 32);
        }
    }

    const int pch = cbase + (lane & 15);
    const float mu2 = g_mu[64 + pch], rs2 = g_rs[64 + pch];
    const float gg2 = g2[pch], bb2 = b2v[pch];
    float* slab = (float*)(smem + G2_OFF_SLAB + w * G2_SLABW);

#pragma unroll
    for (int grp = 0; grp < 4; ++grp) {
        float D[5][4];
#pragma unroll
        for (int nt = 0; nt < 5; ++nt)
#pragma unroll
            for (int j = 0; j < 4; ++j) D[nt][j] = 0.f;

#pragma unroll
        for (int nt = 0; nt < 5; ++nt) {
            const int ebase = grp * 40 + nt * 8;
            const uint32_t brow = (uint32_t)(ebase + (lane & 7)) * G2_ROWB
                                + ((lane >> 3) & 1) * 16;
#pragma unroll
            for (int kc = 0; kc < 4; ++kc) {
                uint32_t bh[2], bl[2];
                ldsm_x2(bh, sbase + G2_OFF_BHI + brow + kc * 32);
                ldsm_x2(bl, sbase + G2_OFF_BLO + brow + kc * 32);
                mma_bf16(D[nt], ahi[kc], bh);
                mma_bf16(D[nt], ahi[kc], bl);
                mma_bf16(D[nt], alo[kc], bh);
            }
        }
        {
            const int r0 = lane >> 2;
            const int c0 = 2 * (lane & 3);
#pragma unroll
            for (int nt = 0; nt < 5; ++nt) {
                const int col = nt * 8 + c0;
                slab[r0 * 44 + col]           = D[nt][0];
                slab[r0 * 44 + col + 1]       = D[nt][1];
                slab[(r0 + 8) * 44 + col]     = D[nt][2];
                slab[(r0 + 8) * 44 + col + 1] = D[nt][3];
            }
        }
        __syncwarp();
        {
            const int ch = lane & 15;
            const int ph = lane >> 4;
            const float* row = slab + ch * 44 + ph * 20;
            float h[20], hmax = 0.f;
#pragma unroll
            for (int k = 0; k < 20; ++k) {
                float y = row[k];
                h[k] = fmaxf(fmaf((y - mu2) * rs2, gg2, bb2), 0.f);
                hmax = fmaxf(hmax, h[k]);
            }
            float se = 0.f, sw = 0.f;
#pragma unroll
            for (int k = 0; k < 20; ++k) {
                float e = __expf(h[k] - hmax);
                se += e;
                sw = fmaf(e, h[k], sw);
            }
            const int p = blockIdx.x * 8 + grp * 2 + ph;
            g_cat[(size_t)p * 192 + 64 + pch] = sw / se;
        }
        __syncwarp();
    }
}

/* ================= cat Gram (192x192) via HMMA + ldmatrix.trans ====== */
#define CG_ROWB 400
__global__ __launch_bounds__(256) void catgram_trans() {
    __shared__ __align__(16) char thi[32 * CG_ROWB];
    __shared__ __align__(16) char tlo[32 * CG_ROWB];
    const int t = threadIdx.x;
    const int w = t >> 5, lane = t & 31;
    const uint32_t uthi = smem_u32(thi), utlo = smem_u32(tlo);
    const int mrow = (w & 3) * 48;
    const int nch  = blockIdx.y * 64 + (w >> 2) * 32;

    float acc[3][4][4];
#pragma unroll
    for (int mt = 0; mt < 3; ++mt)
#pragma unroll
        for (int nt = 0; nt < 4; ++nt)
#pragma unroll
            for (int j = 0; j < 4; ++j) acc[mt][nt][j] = 0.f;

    for (int cc = 0; cc < 16; ++cc) {
        const int rowbase = blockIdx.x * 512 + cc * 32;
        __syncthreads();
#pragma unroll
        for (int l = 0; l < 6; ++l) {
            int q = t + 256 * l;
            int r = q / 48, cg = q % 48;
            float4 v = *(const float4*)(g_cat + (size_t)(rowbase + r) * 192 + cg * 4);
            uint2 hi, lo;
            split4(v, &hi, &lo);
            *(uint2*)(thi + r * CG_ROWB + cg * 8) = hi;
            *(uint2*)(tlo + r * CG_ROWB + cg * 8) = lo;
        }
        __syncthreads();

#pragma unroll
        for (int ks = 0; ks < 2; ++ks) {
            const int rb = ks * 16;
            uint32_t ah[3][4], al[3][4];
#pragma unroll
            for (int mt = 0; mt < 3; ++mt) {
                const int cb = mrow + mt * 16;
                const uint32_t aoff =
                    (uint32_t)(rb + ((lane >> 4) & 1) * 8 + (lane & 7)) * CG_ROWB
                    + (uint32_t)(cb + ((lane >> 3) & 1) * 8) * 2;
                ldsm_x4_t(ah[mt], uthi + aoff);
                ldsm_x4_t(al[mt], utlo + aoff);
            }
#pragma unroll
            for (int nt = 0; nt < 4; ++nt) {
                const int nb = nch + nt * 8;
                const uint32_t boff =
                    (uint32_t)(rb + ((lane >> 3) & 1) * 8 + (lane & 7)) * CG_ROWB
                    + (uint32_t)nb * 2;
                uint32_t bh[2], bl[2];
                ldsm_x2_t(bh, uthi + boff);
                ldsm_x2_t(bl, utlo + boff);
#pragma unroll
                for (int mt = 0; mt < 3; ++mt) {
                    mma_bf16(acc[mt][nt], ah[mt], bh);
                    mma_bf16(acc[mt][nt], ah[mt], bl);
                    mma_bf16(acc[mt][nt], al[mt], bh);
                }
            }
        }
    }
    float* gp = g_cpart + (size_t)blockIdx.x * 36864;
#pragma unroll
    for (int mt = 0; mt < 3; ++mt) {
        const int r0 = mrow + mt * 16 + (lane >> 2);
#pragma unroll
        for (int nt = 0; nt < 4; ++nt) {
            const int c0 = nch + nt * 8 + (lane & 3) * 2;
            gp[r0 * 192 + c0]             = acc[mt][nt][0];
            gp[r0 * 192 + c0 + 1]         = acc[mt][nt][1];
            gp[(r0 + 8) * 192 + c0]       = acc[mt][nt][2];
            gp[(r0 + 8) * 192 + c0 + 1]   = acc[mt][nt][3];
        }
    }
}

/* ================= cat colsum partials =============================== */
__global__ void catsum_kernel() {
    const int t = threadIdx.x;
    if (t >= 192) return;
    const int r0 = blockIdx.x * 256;
    float a = 0.f;
#pragma unroll 8
    for (int r = 0; r < 256; ++r)
        a += g_cat[(size_t)(r0 + r) * 192 + t];
    g_cspart[t * 128 + blockIdx.x] = a;
}

/* ================= reduce cat gram + colsum ========================== */
__global__ void gram3fin_kernel() {
    const int t = threadIdx.x;
    if (blockIdx.x == 144) {
        if (t < 192) {
            float a = 0.f;
#pragma unroll 8
            for (int p = 0; p < 128; ++p) a += g_cspart[t * 128 + p];
            g_catsum[t] = a;
        }
        return;
    }
    const int e = blockIdx.x * 256 + t;
    float a = 0.f;
#pragma unroll 8
    for (int p = 0; p < 64; ++p) a += g_cpart[(size_t)p * 36864 + e];
    g_cgram[e] = a;
}

/* ================= BN3 stats from cat Gram =========================== */
__global__ void bn3fin_kernel() {
    const int o = blockIdx.x;
    const int i = threadIdx.x;
    __shared__ float w[192], rq[192], rm[192];
    w[i] = g_w3t[i * 256 + o];
    __syncthreads();
    float qi = 0.f;
    const float* Gi = g_cgram + i * 192;
#pragma unroll 8
    for (int j = 0; j < 192; ++j) qi = fmaf(Gi[j], w[j], qi);
    rq[i] = qi * w[i];
    rm[i] = w[i] * g_catsum[i];
    __syncthreads();
    for (int s = 96; s >= 3; s >>= 1) {
        if (i < s) { rq[i] += rq[i + s]; rm[i] += rm[i + s]; }
        __syncthreads();
    }
    if (i == 0) {
        const float invN = 1.f / (float)NPTS;
        float mu = (rm[0] + rm[1] + rm[2]) * invN;
        float var = (rq[0] + rq[1] + rq[2]) * invN - mu * mu;
        g_mu[192 + o] = mu;
        g_rs[192 + o] = rsqrtf(var + EPSB);
    }
}

/* ================= GEMM3 via HMMA hi/lo + BN3 + transposed out ======= */
#define G3_ROWB 144
#define G3_OFF_AHI 0
#define G3_OFF_ALO (G3_OFF_AHI + 128 * G3_ROWB)
#define G3_OFF_BHI (G3_OFF_ALO + 128 * G3_ROWB)
#define G3_OFF_BLO (G3_OFF_BHI + 128 * G3_ROWB)
#define G3_SMEM    (G3_OFF_BLO + 128 * G3_ROWB)

__global__ __launch_bounds__(256) void gemm3out_hmma(
        const float* __restrict__ g3, const float* __restrict__ b3,
        float* __restrict__ out) {
    extern __shared__ __align__(16) char smem[];
    const int t = threadIdx.x;
    const int w = t >> 5, lane = t & 31;
    const uint32_t sbase = smem_u32(smem);
    const int mbase = blockIdx.x * 128;
    const int nbase = blockIdx.y * 128;
    const int mrow = (w & 3) * 32;
    const int ncol = (w >> 2) * 64;

    float acc[2][8][4];
#pragma unroll
    for (int mt = 0; mt < 2; ++mt)
#pragma unroll
        for (int nt = 0; nt < 8; ++nt)
#pragma unroll
            for (int j = 0; j < 4; ++j) acc[mt][nt][j] = 0.f;

#pragma unroll
    for (int kc = 0; kc < 3; ++kc) {
#pragma unroll
        for (int l = 0; l < 8; ++l) {
            int q = t + 256 * l;
            int r = q >> 4, kq = (q & 15) * 4;
            float4 v = *(const float4*)(g_cat + (size_t)(mbase + r) * 192
                                        + kc * 64 + kq);
            uint2 hi, lo;
            split4(v, &hi, &lo);
            *(uint2*)(smem + G3_OFF_AHI + r * G3_ROWB + kq * 2) = hi;
            *(uint2*)(smem + G3_OFF_ALO + r * G3_ROWB + kq * 2) = lo;
        }
#pragma unroll
        for (int l = 0; l < 4; ++l) {
            int q = t + 256 * l;
            int r = q >> 3, c16 = q & 7;
            const char* srch = (const char*)g_w3hi
                + (size_t)(nbase + r) * 384 + kc * 128 + c16 * 16;
            const char* srcl = (const char*)g_w3lo
                + (size_t)(nbase + r) * 384 + kc * 128 + c16 * 16;
            *(uint4*)(smem + G3_OFF_BHI + r * G3_ROWB + c16 * 16) = *(const uint4*)srch;
            *(uint4*)(smem + G3_OFF_BLO + r * G3_ROWB + c16 * 16) = *(const uint4*)srcl;
        }
        __syncthreads();

#pragma unroll
        for (int ks = 0; ks < 4; ++ks) {
            uint32_t ah[2][4], al[2][4];
#pragma unroll
            for (int mt = 0; mt < 2; ++mt) {
                const uint32_t aoff =
                    (uint32_t)(mrow + mt * 16 + (lane & 15)) * G3_ROWB
                    + ((lane >> 4) & 1) * 16 + ks * 32;
                ldsm_x4(ah[mt], sbase + G3_OFF_AHI + aoff);
                ldsm_x4(al[mt], sbase + G3_OFF_ALO + aoff);
            }
#pragma unroll
            for (int nt = 0; nt < 8; ++nt) {
                const uint32_t boff =
                    (uint32_t)(ncol + nt * 8 + (lane & 7)) * G3_ROWB
                    + ((lane >> 3) & 1) * 16 + ks * 32;
                uint32_t bh[2], bl[2];
                ldsm_x2(bh, sbase + G3_OFF_BHI + boff);
                ldsm_x2(bl, sbase + G3_OFF_BLO + boff);
#pragma unroll
                for (int mt = 0; mt < 2; ++mt) {
                    mma_bf16(acc[mt][nt], ah[mt], bh);
                    mma_bf16(acc[mt][nt], ah[mt], bl);
                    mma_bf16(acc[mt][nt], al[mt], bh);
                }
            }
        }
        __syncthreads();
    }

    float* slab = (float*)smem;
#pragma unroll
    for (int mt = 0; mt < 2; ++mt) {
        const int r = mrow + mt * 16 + (lane >> 2);
#pragma unroll
        for (int nt = 0; nt < 8; ++nt) {
            const int cl = ncol + nt * 8 + (lane & 3) * 2;
            slab[cl * 132 + r]           = acc[mt][nt][0];
            slab[(cl + 1) * 132 + r]     = acc[mt][nt][1];
            slab[cl * 132 + r + 8]       = acc[mt][nt][2];
            slab[(cl + 1) * 132 + r + 8] = acc[mt][nt][3];
        }
    }
    __syncthreads();

    const int b = mbase >> 12;
    const int nloc = mbase & (NN - 1);
    const int cl = t >> 1;
    const int half = t & 1;
    const int o = nbase + cl;
    const float mu = g_mu[192 + o], rsv = g_rs[192 + o];
    const float gg = g3[o], bb = b3[o];
    const float* srow = slab + cl * 132 + half * 64;
    float* op = out + ((size_t)b * 256 + o) * NN + nloc + half * 64;
#pragma unroll
    for (int j = 0; j < 16; ++j) {
        float4 v = *(const float4*)(srow + j * 4);
        float4 r;
        r.x = fmaxf(fmaf((v.x - mu) * rsv, gg, bb), 0.f);
        r.y = fmaxf(fmaf((v.y - mu) * rsv, gg, bb), 0.f);
        r.z = fmaxf(fmaf((v.z - mu) * rsv, gg, bb), 0.f);
        r.w = fmaxf(fmaf((v.w - mu) * rsv, gg, bb), 0.f);
        *(float4*)(op + j * 4) = r;
    }
}

/* ================= launcher ========================================== */
extern "C" void kernel_launch(void* const* d_in, const int* in_sizes, int n_in,
                              void* d_out, int out_size) {
    const float* x  = (const float*)d_in[0];
    const float* W1 = (const float*)d_in[1];
    const float* g1 = (const float*)d_in[2];
    const float* b1 = (const float*)d_in[3];
    const float* W2 = (const float*)d_in[4];
    const float* g2 = (const float*)d_in[5];
    const float* b2 = (const float*)d_in[6];
    const float* W3 = (const float*)d_in[7];
    const float* g3 = (const float*)d_in[8];
    const float* b3 = (const float*)d_in[9];
    float* out = (float*)d_out;

    cudaFuncSetAttribute(gemm2pool_hmma,
                         cudaFuncAttributeMaxDynamicSharedMemorySize, G2_SMEM);
    cudaFuncSetAttribute(gemm3out_hmma,
                         cudaFuncAttributeMaxDynamicSharedMemorySize, G3_SMEM);

    prep_kernel<<<192, 256>>>(W2, W3);
    knn_kernel<<<dim3(BB, NN / 256), 256>>>(x);

    fgram_kernel<<<128, 256>>>(x, W1);           /* + BN1 finalize */

    h1gram_hmma<<<640, 256>>>(x, W1, g1, b1);    /* profiled slot  */
    gram2fin_kernel<<<65, 256>>>();
    bn2fin_kernel<<<128, 64>>>();

    gemm2pool_hmma<<<M1 / 160, 256, G2_SMEM>>>(x, W1, g1, b1, g2, b2);

    catgram_trans<<<dim3(64, 3), 256>>>();
    catsum_kernel<<<128, 256>>>();
    gram3fin_kernel<<<145, 256>>>();
    bn3fin_kernel<<<256, 192>>>();

    gemm3out_hmma<<<dim3(NPTS / 128, 2), 256, G3_SMEM>>>(g3, b3, out);

    (void)in_sizes; (void)n_in; (void)out_size;
}